// round 4
// baseline (speedup 1.0000x reference)
#include <cuda_runtime.h>
#include <math.h>

#define TT 64
#define BATCH 32
#define POS_V 48
#define WORD_V 32000
#define P_EMB 128
#define W_EMB 512
#define P_HID 256
#define W_HID 1024

// ---------------- scratch (static device memory; no allocs) ----------------
#define OFF_PH0   0
#define OFF_PH1   8192
#define OFF_PC    16384
#define OFF_WH0A  24576
#define OFF_WH0B  57344
#define OFF_WC0   90112
#define OFF_WH1A  122880
#define OFF_WH1B  155648
#define OFF_WC1   188416
#define STATE_TOTAL 221184
#define OFF_LASTW 221184
#define OFF_LASTP 253952
#define OFF_EBUF  262144
#define OFF_PBUF  1310720
#define SCRATCH_TOTAL 1835008

__device__ __align__(256) float g_scratch[SCRATCH_TOTAL];

// ---------------- zero init (states only) ----------------
__global__ void k_zero(float* __restrict__ s) {
    int i = blockIdx.x * 256 + threadIdx.x;   // STATE_TOTAL/4 float4s = 55296
    ((float4*)s)[i] = make_float4(0.f, 0.f, 0.f, 0.f);
}

// ---------------- split-K GEMM for M=32: partial[ks] = X @ W^T ----------------
// X = concat([X0(gather?)|X1|Hold]) along K; W rows per col:
//   LSTM: col (global) = u*4+g  -> Wih/Whh row g*H+u   (gate-interleaved layout)
//   proj: col = n               -> W row n
// Block: CB=64 cols, 128 threads, thread = 4 rows x 4 cols. grid=(ncols/CB, KSPLIT).
template<int CB, bool LSTM>
__global__ void k_gemm(const int* __restrict__ idx,
                       const float* __restrict__ X0, int K0,
                       const float* __restrict__ X1, int K1,
                       const float* __restrict__ Hold, int KH,
                       const float* __restrict__ Wih, const float* __restrict__ Whh,
                       float* __restrict__ pbuf, int H, int Nstride, int kchunk)
{
    constexpr int NT = (CB / 4) * 8;       // 128 threads for CB=64
    __shared__ float Xs[32][36];           // [k][m] transposed
    __shared__ float Ws[32][CB + 4];       // [k][c] transposed
    __shared__ const float* rp[32];

    int tid = threadIdx.x;
    int cg = tid % (CB / 4);
    int rg = tid / (CB / 4);

    float acc[4][4];
#pragma unroll
    for (int r = 0; r < 4; r++)
#pragma unroll
        for (int c = 0; c < 4; c++) acc[r][c] = 0.f;

    int kbeg = blockIdx.y * kchunk, kend = kbeg + kchunk;
    int base = 0;
    for (int seg = 0; seg < 3; seg++) {
        const float* Xb; const float* Wb; int K, ld, cb; bool gather = false;
        if (seg == 0)      { Xb = X0;   K = K0; Wb = Wih; ld = K0 + K1; cb = 0;  gather = (idx != nullptr); }
        else if (seg == 1) { Xb = X1;   K = K1; Wb = Wih; ld = K0 + K1; cb = K0; }
        else               { Xb = Hold; K = KH; Wb = Whh; ld = KH;      cb = 0;  }
        int lo = kbeg > base ? kbeg : base;
        int hi = kend < base + K ? kend : base + K;
        if (lo < hi) {
            if (tid < 32) rp[tid] = gather ? (X0 + (size_t)idx[tid] * K0)
                                           : (Xb + (size_t)tid * K);
            __syncthreads();
            for (int k0 = lo; k0 < hi; k0 += 32) {
                int xoff = k0 - base;
#pragma unroll
                for (int i = tid; i < 256; i += NT) {
                    int m = i >> 3, kq = i & 7;
                    float4 v = *(const float4*)(rp[m] + xoff + kq * 4);
                    Xs[kq*4+0][m] = v.x; Xs[kq*4+1][m] = v.y;
                    Xs[kq*4+2][m] = v.z; Xs[kq*4+3][m] = v.w;
                }
#pragma unroll
                for (int i = tid; i < CB * 8; i += NT) {
                    int c = i >> 3, kq = i & 7;
                    int wr;
                    if (LSTM) wr = (c & 3) * H + blockIdx.x * (CB / 4) + (c >> 2);
                    else      wr = blockIdx.x * CB + c;
                    float4 v = *(const float4*)(Wb + (size_t)wr * ld + cb + xoff + kq * 4);
                    Ws[kq*4+0][c] = v.x; Ws[kq*4+1][c] = v.y;
                    Ws[kq*4+2][c] = v.z; Ws[kq*4+3][c] = v.w;
                }
                __syncthreads();
#pragma unroll
                for (int k = 0; k < 32; k++) {
                    float4 a = *(const float4*)&Xs[k][rg * 4];
                    float4 b = *(const float4*)&Ws[k][cg * 4];
                    acc[0][0] = fmaf(a.x, b.x, acc[0][0]);
                    acc[0][1] = fmaf(a.x, b.y, acc[0][1]);
                    acc[0][2] = fmaf(a.x, b.z, acc[0][2]);
                    acc[0][3] = fmaf(a.x, b.w, acc[0][3]);
                    acc[1][0] = fmaf(a.y, b.x, acc[1][0]);
                    acc[1][1] = fmaf(a.y, b.y, acc[1][1]);
                    acc[1][2] = fmaf(a.y, b.z, acc[1][2]);
                    acc[1][3] = fmaf(a.y, b.w, acc[1][3]);
                    acc[2][0] = fmaf(a.z, b.x, acc[2][0]);
                    acc[2][1] = fmaf(a.z, b.y, acc[2][1]);
                    acc[2][2] = fmaf(a.z, b.z, acc[2][2]);
                    acc[2][3] = fmaf(a.z, b.w, acc[2][3]);
                    acc[3][0] = fmaf(a.w, b.x, acc[3][0]);
                    acc[3][1] = fmaf(a.w, b.y, acc[3][1]);
                    acc[3][2] = fmaf(a.w, b.z, acc[3][2]);
                    acc[3][3] = fmaf(a.w, b.w, acc[3][3]);
                }
                __syncthreads();
            }
        }
        base += K;
    }
#pragma unroll
    for (int r = 0; r < 4; r++) {
        float4 v = make_float4(acc[r][0], acc[r][1], acc[r][2], acc[r][3]);
        *(float4*)&pbuf[(size_t)(blockIdx.y * 32 + rg * 4 + r) * Nstride
                        + blockIdx.x * CB + cg * 4] = v;
    }
}

// ---------------- LSTM epilogue: sum partials + bias, cell update ----------------
__global__ void k_lstm_epi(const float* __restrict__ pbuf, int ksplit,
                           const float* __restrict__ bih, const float* __restrict__ bhh,
                           float* __restrict__ Hnew, float* __restrict__ C, int H)
{
    int gid = blockIdx.x * 256 + threadIdx.x;     // over 32*H
    int m = gid / H, u = gid - m * H;
    float4 s = make_float4(0.f, 0.f, 0.f, 0.f);
    for (int ks = 0; ks < ksplit; ks++) {
        float4 p = *(const float4*)&pbuf[(size_t)(ks * 32 + m) * 4 * H + u * 4];
        s.x += p.x; s.y += p.y; s.z += p.z; s.w += p.w;
    }
    float iv = s.x + bih[u]         + bhh[u];
    float fv = s.y + bih[H + u]     + bhh[H + u];
    float gv = s.z + bih[2 * H + u] + bhh[2 * H + u];
    float ov = s.w + bih[3 * H + u] + bhh[3 * H + u];
    iv = 1.f / (1.f + expf(-iv));
    fv = 1.f / (1.f + expf(-fv));
    gv = tanhf(gv);
    ov = 1.f / (1.f + expf(-ov));
    float c = fv * C[gid] + iv * gv;
    C[gid]    = c;
    Hnew[gid] = ov * tanhf(c);
}

// ---------------- proj epilogue: sum partials + bias (+tanh) ----------------
template<int ACT>
__global__ void k_proj_epi(const float* __restrict__ pbuf, int ksplit,
                           const float* __restrict__ bias, float* __restrict__ out, int N)
{
    int gid = blockIdx.x * 256 + threadIdx.x;     // over 32*N/4
    int m = gid / (N / 4), nq = gid - m * (N / 4);
    float4 s = *(const float4*)&bias[nq * 4];
    for (int ks = 0; ks < ksplit; ks++) {
        float4 p = *(const float4*)&pbuf[(size_t)(ks * 32 + m) * N + nq * 4];
        s.x += p.x; s.y += p.y; s.z += p.z; s.w += p.w;
    }
    if (ACT == 1) { s.x = tanhf(s.x); s.y = tanhf(s.y); s.z = tanhf(s.z); s.w = tanhf(s.w); }
    *(float4*)&out[(size_t)m * N + nq * 4] = s;
}

// ---------------- small single-kernel proj (p2w, tiny) ----------------
template<int JT, int ACT>
__global__ void k_proj(const float* __restrict__ X, int K,
                       const float* __restrict__ W,
                       const float* __restrict__ bias,
                       float* __restrict__ out, int N)
{
    constexpr int OPT  = (32 * JT) / 256;
    constexpr int KQ   = 16;
    constexpr int LDS4 = 17;
    __shared__ float4 Xs[32 * LDS4];
    __shared__ float4 Ws[JT * LDS4];
    int tid = threadIdx.x;
    int jj  = tid % JT;
    int rg  = tid / JT;
    int j   = blockIdx.x * JT + jj;
    float b = bias ? bias[j] : 0.f;
    float acc[OPT];
#pragma unroll
    for (int i = 0; i < OPT; i++) acc[i] = b;
    for (int k0 = 0; k0 < K; k0 += 64) {
        for (int i = tid; i < 32 * KQ; i += 256) {
            int r = i >> 4, kq = i & 15;
            Xs[r * LDS4 + kq] = *(const float4*)(X + (size_t)r * K + k0 + kq * 4);
        }
        for (int i = tid; i < JT * KQ; i += 256) {
            int rr = i >> 4, kq = i & 15;
            Ws[rr * LDS4 + kq] =
                *(const float4*)(W + (size_t)(blockIdx.x * JT + rr) * K + k0 + kq * 4);
        }
        __syncthreads();
#pragma unroll
        for (int kq = 0; kq < KQ; kq++) {
            float4 wv = Ws[jj * LDS4 + kq];
#pragma unroll
            for (int i = 0; i < OPT; i++) {
                float4 xv = Xs[(rg * OPT + i) * LDS4 + kq];
                acc[i] = fmaf(xv.x, wv.x, acc[i]);
                acc[i] = fmaf(xv.y, wv.y, acc[i]);
                acc[i] = fmaf(xv.z, wv.z, acc[i]);
                acc[i] = fmaf(xv.w, wv.w, acc[i]);
            }
        }
        __syncthreads();
    }
#pragma unroll
    for (int i = 0; i < OPT; i++) {
        float v = acc[i];
        if (ACT == 1) v = tanhf(v);
        out[(size_t)(rg * OPT + i) * N + j] = v;
    }
}

// ---------------- pos head: logits + log_softmax (48-way) ----------------
__global__ void k_pos_out(const float* __restrict__ ph, const float* __restrict__ W,
                          const float* __restrict__ bias, float* __restrict__ out)
{
    int r = blockIdx.x;
    int j = threadIdx.x;
    __shared__ float vals[48];
    __shared__ float s_lse;
    float v = 0.f;
    if (j < 48) {
        v = bias[j];
        const float4* xp = (const float4*)(ph + r * 256);
        const float4* wp = (const float4*)(W + j * 256);
#pragma unroll 8
        for (int k = 0; k < 64; k++) {
            float4 x = xp[k], w = wp[k];
            v = fmaf(x.x, w.x, v); v = fmaf(x.y, w.y, v);
            v = fmaf(x.z, w.z, v); v = fmaf(x.w, w.w, v);
        }
        vals[j] = v;
    }
    __syncthreads();
    if (threadIdx.x == 0) {
        float m = -1e30f;
        for (int k = 0; k < 48; k++) m = fmaxf(m, vals[k]);
        float s = 0.f;
        for (int k = 0; k < 48; k++) s += expf(vals[k] - m);
        s_lse = m + logf(s);
    }
    __syncthreads();
    if (j < 48) out[r * 48 + j] = v - s_lse;
}

// ---------------- big final GEMM: out[2048,32000] = E[2048,512] @ W[32000,512]^T + b --
__global__ void k_big(const float* __restrict__ E, const float* __restrict__ W,
                      const float* __restrict__ bias, float* __restrict__ out)
{
    __shared__ float Es[16][68];
    __shared__ float Bs[16][68];
    int tid = threadIdx.x;
    int cg = tid % 16, rg = tid / 16;
    int mbase = blockIdx.y * 64, nbase = blockIdx.x * 64;

    float acc[4][4];
#pragma unroll
    for (int r = 0; r < 4; r++)
#pragma unroll
        for (int c = 0; c < 4; c++) acc[r][c] = 0.f;

    int ml = tid >> 2, kq = tid & 3;
    for (int k0 = 0; k0 < 512; k0 += 16) {
        float4 v = *(const float4*)(E + (size_t)(mbase + ml) * 512 + k0 + kq * 4);
        Es[kq*4+0][ml] = v.x; Es[kq*4+1][ml] = v.y;
        Es[kq*4+2][ml] = v.z; Es[kq*4+3][ml] = v.w;
        float4 w = *(const float4*)(W + (size_t)(nbase + ml) * 512 + k0 + kq * 4);
        Bs[kq*4+0][ml] = w.x; Bs[kq*4+1][ml] = w.y;
        Bs[kq*4+2][ml] = w.z; Bs[kq*4+3][ml] = w.w;
        __syncthreads();
#pragma unroll
        for (int k = 0; k < 16; k++) {
            float4 a = *(const float4*)&Es[k][rg * 4];
            float4 b = *(const float4*)&Bs[k][cg * 4];
            acc[0][0] = fmaf(a.x, b.x, acc[0][0]);
            acc[0][1] = fmaf(a.x, b.y, acc[0][1]);
            acc[0][2] = fmaf(a.x, b.z, acc[0][2]);
            acc[0][3] = fmaf(a.x, b.w, acc[0][3]);
            acc[1][0] = fmaf(a.y, b.x, acc[1][0]);
            acc[1][1] = fmaf(a.y, b.y, acc[1][1]);
            acc[1][2] = fmaf(a.y, b.z, acc[1][2]);
            acc[1][3] = fmaf(a.y, b.w, acc[1][3]);
            acc[2][0] = fmaf(a.z, b.x, acc[2][0]);
            acc[2][1] = fmaf(a.z, b.y, acc[2][1]);
            acc[2][2] = fmaf(a.z, b.z, acc[2][2]);
            acc[2][3] = fmaf(a.z, b.w, acc[2][3]);
            acc[3][0] = fmaf(a.w, b.x, acc[3][0]);
            acc[3][1] = fmaf(a.w, b.y, acc[3][1]);
            acc[3][2] = fmaf(a.w, b.z, acc[3][2]);
            acc[3][3] = fmaf(a.w, b.w, acc[3][3]);
        }
        __syncthreads();
    }
    float4 bv = *(const float4*)&bias[nbase + cg * 4];
#pragma unroll
    for (int r = 0; r < 4; r++) {
        float4 v = make_float4(acc[r][0] + bv.x, acc[r][1] + bv.y,
                               acc[r][2] + bv.z, acc[r][3] + bv.w);
        *(float4*)&out[(size_t)(mbase + rg * 4 + r) * WORD_V + nbase + cg * 4] = v;
    }
}

// ---------------- final word log_softmax over all T*B rows ----------------
__global__ void k_wnorm(float* __restrict__ wout)
{
    float* p = wout + (size_t)blockIdx.x * WORD_V;
    __shared__ float red[256];
    int tid = threadIdx.x;

    float m = -1e30f;
    for (int k = tid; k < WORD_V; k += 256) m = fmaxf(m, p[k]);
    red[tid] = m; __syncthreads();
    for (int s = 128; s > 0; s >>= 1) { if (tid < s) red[tid] = fmaxf(red[tid], red[tid + s]); __syncthreads(); }
    m = red[0]; __syncthreads();

    float s = 0.f;
    for (int k = tid; k < WORD_V; k += 256) s += expf(p[k] - m);
    red[tid] = s; __syncthreads();
    for (int st = 128; st > 0; st >>= 1) { if (tid < st) red[tid] += red[tid + st]; __syncthreads(); }
    float lse = m + logf(red[0]);

    for (int k = tid; k < WORD_V; k += 256) p[k] -= lse;
}

// ---------------- launch ----------------
extern "C" void kernel_launch(void* const* d_in, const int* in_sizes, int n_in,
                              void* d_out, int out_size)
{
    const int*   pos          = (const int*)  d_in[0];
    const int*   word         = (const int*)  d_in[1];
    const float* pos_emb_W    = (const float*)d_in[2];
    const float* word_emb_W   = (const float*)d_in[3];
    const float* w2p_W        = (const float*)d_in[4];
    const float* w2p_b        = (const float*)d_in[5];
    const float* p2w_W        = (const float*)d_in[6];
    const float* p2w_b        = (const float*)d_in[7];
    const float* p_Wih0       = (const float*)d_in[8];
    const float* p_Whh0       = (const float*)d_in[9];
    const float* p_bih0       = (const float*)d_in[10];
    const float* p_bhh0       = (const float*)d_in[11];
    const float* w_Wih0       = (const float*)d_in[12];
    const float* w_Whh0       = (const float*)d_in[13];
    const float* w_bih0       = (const float*)d_in[14];
    const float* w_bhh0       = (const float*)d_in[15];
    const float* w_Wih1       = (const float*)d_in[16];
    const float* w_Whh1       = (const float*)d_in[17];
    const float* w_bih1       = (const float*)d_in[18];
    const float* w_bhh1       = (const float*)d_in[19];
    const float* pos_proj_W   = (const float*)d_in[20];
    const float* pos_proj_b   = (const float*)d_in[21];
    const float* word_proj1_W = (const float*)d_in[22];
    const float* word_proj1_b = (const float*)d_in[23];
    const float* word_proj2_b = (const float*)d_in[24];

    float* scratch = nullptr;
    cudaGetSymbolAddress((void**)&scratch, g_scratch);

    float* ph[2]  = { scratch + OFF_PH0,  scratch + OFF_PH1  };
    float* pc     =   scratch + OFF_PC;
    float* wh0[2] = { scratch + OFF_WH0A, scratch + OFF_WH0B };
    float* wc0    =   scratch + OFF_WC0;
    float* wh1[2] = { scratch + OFF_WH1A, scratch + OFF_WH1B };
    float* wc1    =   scratch + OFF_WC1;
    float* lastw  =   scratch + OFF_LASTW;
    float* lastp  =   scratch + OFF_LASTP;
    float* ebuf   =   scratch + OFF_EBUF;
    float* pbuf   =   scratch + OFF_PBUF;

    float* pout = (float*)d_out;
    float* wout = pout + (size_t)TT * BATCH * POS_V;

    k_zero<<<STATE_TOTAL / 4 / 256, 256>>>(scratch);

    for (int t = 0; t < TT; t++) {
        int cur = t & 1, nxt = cur ^ 1;

        // last_w = tanh(w_h1_old @ w2p^T + b)   [K=1024, N=1024, split-4]
        k_gemm<64, false><<<dim3(16, 4), 128>>>(nullptr, wh1[cur], W_HID,
                                                nullptr, 0, nullptr, 0,
                                                w2p_W, nullptr, pbuf, 0, W_HID, 256);
        k_proj_epi<1><<<32, 256>>>(pbuf, 4, w2p_b, lastw, W_HID);

        // POS LSTM: x = [p_emb_t | last_w], h=ph  [K=1408, 4H=1024, split-4]
        k_gemm<64, true><<<dim3(16, 4), 128>>>(pos + t * BATCH, pos_emb_W, P_EMB,
                                               lastw, W_HID, ph[cur], P_HID,
                                               p_Wih0, p_Whh0, pbuf, P_HID, 4 * P_HID, 352);
        k_lstm_epi<<<32, 256>>>(pbuf, 4, p_bih0, p_bhh0, ph[nxt], pc, P_HID);

        // last_p = tanh(p_h_new @ p2w^T + b)  (tiny)
        k_proj<8, 1><<<P_HID / 8, 256>>>(ph[nxt], P_HID, p2w_W, p2w_b, lastp, P_HID);

        // pos logits + log_softmax
        k_pos_out<<<BATCH, 64>>>(ph[nxt], pos_proj_W, pos_proj_b,
                                 pout + (size_t)t * BATCH * POS_V);

        // word LSTM 0: x = [w_emb_t | last_p]  [K=1792, 4H=4096, split-2]
        k_gemm<64, true><<<dim3(64, 2), 128>>>(word + t * BATCH, word_emb_W, W_EMB,
                                               lastp, P_HID, wh0[cur], W_HID,
                                               w_Wih0, w_Whh0, pbuf, W_HID, 4 * W_HID, 896);
        k_lstm_epi<<<128, 256>>>(pbuf, 2, w_bih0, w_bhh0, wh0[nxt], wc0, W_HID);

        // word LSTM 1: x = w_h0_new  [K=2048, 4H=4096, split-2]
        k_gemm<64, true><<<dim3(64, 2), 128>>>(nullptr, wh0[nxt], W_HID,
                                               nullptr, 0, wh1[cur], W_HID,
                                               w_Wih1, w_Whh1, pbuf, W_HID, 4 * W_HID, 1024);
        k_lstm_epi<<<128, 256>>>(pbuf, 2, w_bih1, w_bhh1, wh1[nxt], wc1, W_HID);

        // e_t = w_h1_new @ proj1^T + b  [K=1024, N=512, split-4] -> stored for final GEMM
        k_gemm<64, false><<<dim3(8, 4), 128>>>(nullptr, wh1[nxt], W_HID,
                                               nullptr, 0, nullptr, 0,
                                               word_proj1_W, nullptr, pbuf, 0, W_EMB, 256);
        k_proj_epi<0><<<16, 256>>>(pbuf, 4, word_proj1_b, ebuf + (size_t)t * BATCH * W_EMB, W_EMB);
    }

    // ONE big word-logits GEMM over all timesteps, then log-softmax
    k_big<<<dim3(WORD_V / 64, (TT * BATCH) / 64), 256>>>(ebuf, word_emb_W, word_proj2_b, wout);
    k_wnorm<<<TT * BATCH, 256>>>(wout);
}

// round 5
// speedup vs baseline: 1.9150x; 1.9150x over previous
#include <cuda_runtime.h>
#include <math.h>

#define TT 64
#define WORD_V 32000
#define G 148

__device__ __align__(16) float g_ph[32 * 256];
__device__ __align__(16) float g_pc[32 * 256];
__device__ __align__(16) float g_wh0[32 * 1024];
__device__ __align__(16) float g_wc0[32 * 1024];
__device__ __align__(16) float g_wh1[32 * 1024];
__device__ __align__(16) float g_wc1[32 * 1024];
__device__ __align__(16) float g_lastw[32 * 1024];
__device__ __align__(16) float g_lastp[32 * 256];
__device__ __align__(16) float g_ebuf[2048 * 512];
__device__ __align__(16) float g_PIH[2048 * 1024];
__device__ __align__(16) float g_WIH0[2048 * 4096];
__device__ __align__(16) float g_pbuf[1048576];
__device__ unsigned g_cnt;
__device__ volatile unsigned g_gen;

__device__ __forceinline__ void gridbar() {
    __threadfence();
    __syncthreads();
    if (threadIdx.x == 0) {
        unsigned gen = g_gen;
        if (atomicAdd(&g_cnt, 1u) == G - 1) { g_cnt = 0; __threadfence(); g_gen = gen + 1; }
        else { while (g_gen == gen) { } }
    }
    __syncthreads();
}

__device__ __forceinline__ float sigf(float x) { return 1.f / (1.f + expf(-x)); }

// stage GEMM: tasks = 32x128 col-tile x split-K over concat([Xa|Xb]) @ Wrow(col)^T
// H>0: col gc -> W row (gc&3)*H+(gc>>2) (gate-interleaved). H==0: gc<ws -> Wa row gc else Wc row gc-ws.
// mode 0: partial to out[ks][32][ostride]; mode 2: final tanh(acc+bias) to out[32][ostride].
__device__ __noinline__ void gstage(
    int tid, int cta, float* sX, float* sW, int ncolt, int ksplit, int kc,
    const float* Xa, int Ka, const float* Wa, int lda, int cba,
    const float* Xb, int Kb, const float* Wb, int ldb, int cbb,
    int H, int ws, const float* Wc,
    float* out, int ostride, int mode, const float* bias)
{
    const int rg = tid >> 5, cg = tid & 31;
    const int ntasks = ncolt * ksplit;
    for (int task = cta; task < ntasks; task += G) {
        const int ct = task % ncolt, ks = task / ncolt;
        const int kbeg = ks * kc, kend = kbeg + kc;
        float acc[4][4];
#pragma unroll
        for (int r = 0; r < 4; r++)
#pragma unroll
            for (int c = 0; c < 4; c++) acc[r][c] = 0.f;
        int base = 0;
#pragma unroll 1
        for (int seg = 0; seg < 2; seg++) {
            const float* Xp = seg ? Xb : Xa;
            const float* Wp = seg ? Wb : Wa;
            const int K = seg ? Kb : Ka, ld = seg ? ldb : lda, cb = seg ? cbb : cba;
            if (K > 0) {
                int lo = kbeg > base ? kbeg : base;
                int hi = kend < base + K ? kend : base + K;
#pragma unroll 1
                for (int k0 = lo; k0 < hi; k0 += 16) {
                    int xo = k0 - base;
                    if (tid < 128) {
                        int m = tid & 31, kq = tid >> 5;
                        float4 v = __ldcg((const float4*)(Xp + (size_t)m * K + xo + kq * 4));
                        sX[(kq * 4 + 0) * 36 + m] = v.x; sX[(kq * 4 + 1) * 36 + m] = v.y;
                        sX[(kq * 4 + 2) * 36 + m] = v.z; sX[(kq * 4 + 3) * 36 + m] = v.w;
                    }
#pragma unroll
                    for (int i = tid; i < 512; i += 256) {
                        int c = i & 127, kq = i >> 7;
                        int gc = ct * 128 + c;
                        const float* wr;
                        if (H > 0)        wr = Wp + (size_t)((gc & 3) * H + (gc >> 2)) * ld + cb;
                        else if (gc < ws) wr = Wp + (size_t)gc * ld + cb;
                        else              wr = Wc + (size_t)(gc - ws) * ld + cb;
                        float4 v = __ldg((const float4*)(wr + xo + kq * 4));
                        sW[(kq * 4 + 0) * 132 + c] = v.x; sW[(kq * 4 + 1) * 132 + c] = v.y;
                        sW[(kq * 4 + 2) * 132 + c] = v.z; sW[(kq * 4 + 3) * 132 + c] = v.w;
                    }
                    __syncthreads();
#pragma unroll
                    for (int k = 0; k < 16; k++) {
                        float4 a = *(const float4*)&sX[k * 36 + rg * 4];
                        float4 b = *(const float4*)&sW[k * 132 + cg * 4];
                        float av[4] = {a.x, a.y, a.z, a.w}, bv[4] = {b.x, b.y, b.z, b.w};
#pragma unroll
                        for (int r = 0; r < 4; r++)
#pragma unroll
                            for (int c = 0; c < 4; c++)
                                acc[r][c] = fmaf(av[r], bv[c], acc[r][c]);
                    }
                    __syncthreads();
                }
            }
            base += K;
        }
        int oc = ct * 128 + cg * 4;
        if (mode == 0) {
#pragma unroll
            for (int r = 0; r < 4; r++)
                *(float4*)&out[(size_t)(ks * 32 + rg * 4 + r) * ostride + oc] =
                    make_float4(acc[r][0], acc[r][1], acc[r][2], acc[r][3]);
        } else {
            float4 bv = *(const float4*)&bias[oc];
#pragma unroll
            for (int r = 0; r < 4; r++)
                *(float4*)&out[(size_t)(rg * 4 + r) * ostride + oc] =
                    make_float4(tanhf(acc[r][0] + bv.x), tanhf(acc[r][1] + bv.y),
                                tanhf(acc[r][2] + bv.z), tanhf(acc[r][3] + bv.w));
        }
    }
}

__global__ void __launch_bounds__(256, 1) k_loop(
    const float* __restrict__ w2p_W, const float* __restrict__ w2p_b,
    const float* __restrict__ p2w_W, const float* __restrict__ p2w_b,
    const float* __restrict__ p_Wih0, const float* __restrict__ p_Whh0,
    const float* __restrict__ p_bih0, const float* __restrict__ p_bhh0,
    const float* __restrict__ w_Wih0, const float* __restrict__ w_Whh0,
    const float* __restrict__ w_bih0, const float* __restrict__ w_bhh0,
    const float* __restrict__ w_Wih1, const float* __restrict__ w_Whh1,
    const float* __restrict__ w_bih1, const float* __restrict__ w_bhh1,
    const float* __restrict__ pos_proj_W, const float* __restrict__ pos_proj_b,
    const float* __restrict__ word_proj1_W, const float* __restrict__ word_proj1_b,
    float* __restrict__ pout)
{
    __shared__ float sX[16 * 36];
    __shared__ float sW[16 * 132];
    const int tid = threadIdx.x, cta = blockIdx.x;
    const int gt = cta * 256 + tid;

    { // zero states
        float4 z = make_float4(0.f, 0.f, 0.f, 0.f);
        if (gt < 2048) { ((float4*)g_ph)[gt] = z; ((float4*)g_pc)[gt] = z; }
        if (gt < 8192) { ((float4*)g_wh0)[gt] = z; ((float4*)g_wc0)[gt] = z;
                         ((float4*)g_wh1)[gt] = z; ((float4*)g_wc1)[gt] = z; }
    }
    gridbar();

    for (int t = 0; t <= TT; t++) {
        // A: pbuf = wh1 @ [w2p_W | word_proj1_W]^T  (1536 cols, K=1024, split-8)
        gstage(tid, cta, sX, sW, 12, 8, 128, g_wh1, 1024, w2p_W, 1024, 0,
               nullptr, 0, nullptr, 0, 0, 0, 1024, word_proj1_W, g_pbuf, 1536, 0, nullptr);
        gridbar();
        // B: lastw = tanh(sum+b);  e_{t-1} = sum+b
        for (int gid = gt; gid < 12288; gid += G * 256) {
            if (gid < 8192) {
                int m = gid >> 8, cq = gid & 255;
                float4 s = *(const float4*)&w2p_b[cq * 4];
#pragma unroll
                for (int ks = 0; ks < 8; ks++) {
                    float4 p = __ldcg((const float4*)&g_pbuf[(size_t)(ks * 32 + m) * 1536 + cq * 4]);
                    s.x += p.x; s.y += p.y; s.z += p.z; s.w += p.w;
                }
                *(float4*)&g_lastw[m * 1024 + cq * 4] =
                    make_float4(tanhf(s.x), tanhf(s.y), tanhf(s.z), tanhf(s.w));
            } else if (t >= 1) {
                int i2 = gid - 8192, m = i2 >> 7, cq = i2 & 127;
                float4 s = *(const float4*)&word_proj1_b[cq * 4];
#pragma unroll
                for (int ks = 0; ks < 8; ks++) {
                    float4 p = __ldcg((const float4*)&g_pbuf[(size_t)(ks * 32 + m) * 1536 + 1024 + cq * 4]);
                    s.x += p.x; s.y += p.y; s.z += p.z; s.w += p.w;
                }
                *(float4*)&g_ebuf[(size_t)((t - 1) * 32 + m) * 512 + cq * 4] = s;
            }
        }
        if (t == TT) break;
        gridbar();
        // C: pos gates (K = lastw 1024 + ph 256; emb hoisted into PIH)
        gstage(tid, cta, sX, sW, 8, 10, 128, g_lastw, 1024, p_Wih0, 1152, 128,
               g_ph, 256, p_Whh0, 256, 0, 256, 0, nullptr, g_pbuf, 1024, 0, nullptr);
        gridbar();
        // D: pos cell update
        for (int gid = gt; gid < 8192; gid += G * 256) {
            int m = gid >> 8, u = gid & 255;
            float4 s = __ldg((const float4*)&g_PIH[(size_t)(t * 32 + m) * 1024 + u * 4]);
#pragma unroll
            for (int ks = 0; ks < 10; ks++) {
                float4 p = __ldcg((const float4*)&g_pbuf[(size_t)(ks * 32 + m) * 1024 + u * 4]);
                s.x += p.x; s.y += p.y; s.z += p.z; s.w += p.w;
            }
            float iv = sigf(s.x + __ldg(&p_bih0[u]) + __ldg(&p_bhh0[u]));
            float fv = sigf(s.y + __ldg(&p_bih0[256 + u]) + __ldg(&p_bhh0[256 + u]));
            float gv = tanhf(s.z + __ldg(&p_bih0[512 + u]) + __ldg(&p_bhh0[512 + u]));
            float ov = sigf(s.w + __ldg(&p_bih0[768 + u]) + __ldg(&p_bhh0[768 + u]));
            float c = fv * __ldcg(&g_pc[gid]) + iv * gv;
            g_pc[gid] = c; g_ph[gid] = ov * tanhf(c);
        }
        gridbar();
        // E: lastp (CTAs 0-1) + pos_out (CTAs 2-33)
        gstage(tid, cta, sX, sW, 2, 1, 256, g_ph, 256, p2w_W, 256, 0,
               nullptr, 0, nullptr, 0, 0, 0, 1 << 30, nullptr, g_lastp, 256, 2, p2w_b);
        if (cta >= 2 && cta < 34) {
            int r = cta - 2;
            float v = 0.f;
            if (tid < 48) {
                v = __ldg(&pos_proj_b[tid]);
                const float4* xp = (const float4*)(g_ph + r * 256);
                const float4* wp = (const float4*)(pos_proj_W + tid * 256);
#pragma unroll 8
                for (int k = 0; k < 64; k++) {
                    float4 x = __ldcg(xp + k), w = __ldg(wp + k);
                    v = fmaf(x.x, w.x, v); v = fmaf(x.y, w.y, v);
                    v = fmaf(x.z, w.z, v); v = fmaf(x.w, w.w, v);
                }
                sW[tid] = v;
            }
            __syncthreads();
            if (tid == 0) {
                float mx = -1e30f;
                for (int k = 0; k < 48; k++) mx = fmaxf(mx, sW[k]);
                float sm = 0.f;
                for (int k = 0; k < 48; k++) sm += expf(sW[k] - mx);
                sW[48] = mx + logf(sm);
            }
            __syncthreads();
            if (tid < 48) pout[((size_t)t * 32 + r) * 48 + tid] = v - sW[48];
        }
        gridbar();
        // F: word LSTM0 gates (K = lastp 256 + wh0 1024; emb hoisted into WIH0)
        gstage(tid, cta, sX, sW, 32, 5, 256, g_lastp, 256, w_Wih0, 768, 512,
               g_wh0, 1024, w_Whh0, 1024, 0, 1024, 0, nullptr, g_pbuf, 4096, 0, nullptr);
        gridbar();
        // G: word LSTM0 cell
        for (int gid = gt; gid < 32768; gid += G * 256) {
            int m = gid >> 10, u = gid & 1023;
            float4 s = __ldg((const float4*)&g_WIH0[(size_t)(t * 32 + m) * 4096 + u * 4]);
#pragma unroll
            for (int ks = 0; ks < 5; ks++) {
                float4 p = __ldcg((const float4*)&g_pbuf[(size_t)(ks * 32 + m) * 4096 + u * 4]);
                s.x += p.x; s.y += p.y; s.z += p.z; s.w += p.w;
            }
            float iv = sigf(s.x + __ldg(&w_bih0[u]) + __ldg(&w_bhh0[u]));
            float fv = sigf(s.y + __ldg(&w_bih0[1024 + u]) + __ldg(&w_bhh0[1024 + u]));
            float gv = tanhf(s.z + __ldg(&w_bih0[2048 + u]) + __ldg(&w_bhh0[2048 + u]));
            float ov = sigf(s.w + __ldg(&w_bih0[3072 + u]) + __ldg(&w_bhh0[3072 + u]));
            float c = fv * __ldcg(&g_wc0[gid]) + iv * gv;
            g_wc0[gid] = c; g_wh0[gid] = ov * tanhf(c);
        }
        gridbar();
        // H: word LSTM1 gates (K = wh0 1024 + wh1 1024)
        gstage(tid, cta, sX, sW, 32, 8, 256, g_wh0, 1024, w_Wih1, 1024, 0,
               g_wh1, 1024, w_Whh1, 1024, 0, 1024, 0, nullptr, g_pbuf, 4096, 0, nullptr);
        gridbar();
        // I: word LSTM1 cell
        for (int gid = gt; gid < 32768; gid += G * 256) {
            int m = gid >> 10, u = gid & 1023;
            float4 s = make_float4(0.f, 0.f, 0.f, 0.f);
#pragma unroll
            for (int ks = 0; ks < 8; ks++) {
                float4 p = __ldcg((const float4*)&g_pbuf[(size_t)(ks * 32 + m) * 4096 + u * 4]);
                s.x += p.x; s.y += p.y; s.z += p.z; s.w += p.w;
            }
            float iv = sigf(s.x + __ldg(&w_bih1[u]) + __ldg(&w_bhh1[u]));
            float fv = sigf(s.y + __ldg(&w_bih1[1024 + u]) + __ldg(&w_bhh1[1024 + u]));
            float gv = tanhf(s.z + __ldg(&w_bih1[2048 + u]) + __ldg(&w_bhh1[2048 + u]));
            float ov = sigf(s.w + __ldg(&w_bih1[3072 + u]) + __ldg(&w_bhh1[3072 + u]));
            float c = fv * __ldcg(&g_wc1[gid]) + iv * gv;
            g_wc1[gid] = c; g_wh1[gid] = ov * tanhf(c);
        }
        gridbar();
    }
}

// precompute: out[2048][N] = table[idx[m]] @ Wrow^T (gate-interleaved rows, emb at cb 0)
__global__ void __launch_bounds__(256, 2) k_pre(
    const int* __restrict__ idx, const float* __restrict__ table, int K,
    const float* __restrict__ W, int ldW, int H, float* __restrict__ out, int N)
{
    __shared__ float As[16][132];
    __shared__ float Bs[16][132];
    __shared__ const float* rp[128];
    int tid = threadIdx.x;
    int mb = blockIdx.y * 128, nb = blockIdx.x * 128;
    if (tid < 128) rp[tid] = table + (size_t)idx[mb + tid] * K;
    __syncthreads();
    float acc[8][8];
#pragma unroll
    for (int r = 0; r < 8; r++)
#pragma unroll
        for (int c = 0; c < 8; c++) acc[r][c] = 0.f;
    int rg = tid >> 4, cg = tid & 15;
    for (int k0 = 0; k0 < K; k0 += 16) {
#pragma unroll
        for (int i = tid; i < 512; i += 256) {
            int m = i & 127, kq = i >> 7;
            float4 v = *(const float4*)(rp[m] + k0 + kq * 4);
            As[kq * 4 + 0][m] = v.x; As[kq * 4 + 1][m] = v.y;
            As[kq * 4 + 2][m] = v.z; As[kq * 4 + 3][m] = v.w;
        }
#pragma unroll
        for (int i = tid; i < 512; i += 256) {
            int c = i & 127, kq = i >> 7;
            int gc = nb + c;
            float4 v = __ldg((const float4*)(W + (size_t)((gc & 3) * H + (gc >> 2)) * ldW + k0 + kq * 4));
            Bs[kq * 4 + 0][c] = v.x; Bs[kq * 4 + 1][c] = v.y;
            Bs[kq * 4 + 2][c] = v.z; Bs[kq * 4 + 3][c] = v.w;
        }
        __syncthreads();
#pragma unroll
        for (int k = 0; k < 16; k++) {
            float4 a0 = *(const float4*)&As[k][rg * 8];
            float4 a1 = *(const float4*)&As[k][rg * 8 + 4];
            float4 b0 = *(const float4*)&Bs[k][cg * 8];
            float4 b1 = *(const float4*)&Bs[k][cg * 8 + 4];
            float av[8] = {a0.x, a0.y, a0.z, a0.w, a1.x, a1.y, a1.z, a1.w};
            float bv[8] = {b0.x, b0.y, b0.z, b0.w, b1.x, b1.y, b1.z, b1.w};
#pragma unroll
            for (int r = 0; r < 8; r++)
#pragma unroll
                for (int c = 0; c < 8; c++) acc[r][c] = fmaf(av[r], bv[c], acc[r][c]);
        }
        __syncthreads();
    }
#pragma unroll
    for (int r = 0; r < 8; r++) {
        float* op = out + (size_t)(mb + rg * 8 + r) * N + nb + cg * 8;
        *(float4*)op = make_float4(acc[r][0], acc[r][1], acc[r][2], acc[r][3]);
        *(float4*)(op + 4) = make_float4(acc[r][4], acc[r][5], acc[r][6], acc[r][7]);
    }
}

__global__ void __launch_bounds__(256, 2) k_big(
    const float* __restrict__ W, const float* __restrict__ bias, float* __restrict__ out)
{
    __shared__ float As[16][132];
    __shared__ float Bs[16][132];
    int tid = threadIdx.x;
    int mb = blockIdx.y * 128, nb = blockIdx.x * 128;
    float acc[8][8];
#pragma unroll
    for (int r = 0; r < 8; r++)
#pragma unroll
        for (int c = 0; c < 8; c++) acc[r][c] = 0.f;
    int rg = tid >> 4, cg = tid & 15;
    for (int k0 = 0; k0 < 512; k0 += 16) {
#pragma unroll
        for (int i = tid; i < 512; i += 256) {
            int m = i & 127, kq = i >> 7;
            float4 v = *(const float4*)(g_ebuf + (size_t)(mb + m) * 512 + k0 + kq * 4);
            As[kq * 4 + 0][m] = v.x; As[kq * 4 + 1][m] = v.y;
            As[kq * 4 + 2][m] = v.z; As[kq * 4 + 3][m] = v.w;
        }
#pragma unroll
        for (int i = tid; i < 512; i += 256) {
            int c = i & 127, kq = i >> 7;
            float4 v = __ldg((const float4*)(W + (size_t)(nb + c) * 512 + k0 + kq * 4));
            Bs[kq * 4 + 0][c] = v.x; Bs[kq * 4 + 1][c] = v.y;
            Bs[kq * 4 + 2][c] = v.z; Bs[kq * 4 + 3][c] = v.w;
        }
        __syncthreads();
#pragma unroll
        for (int k = 0; k < 16; k++) {
            float4 a0 = *(const float4*)&As[k][rg * 8];
            float4 a1 = *(const float4*)&As[k][rg * 8 + 4];
            float4 b0 = *(const float4*)&Bs[k][cg * 8];
            float4 b1 = *(const float4*)&Bs[k][cg * 8 + 4];
            float av[8] = {a0.x, a0.y, a0.z, a0.w, a1.x, a1.y, a1.z, a1.w};
            float bv[8] = {b0.x, b0.y, b0.z, b0.w, b1.x, b1.y, b1.z, b1.w};
#pragma unroll
            for (int r = 0; r < 8; r++)
#pragma unroll
                for (int c = 0; c < 8; c++) acc[r][c] = fmaf(av[r], bv[c], acc[r][c]);
        }
        __syncthreads();
    }
    float4 bv0 = *(const float4*)&bias[nb + cg * 8];
    float4 bv1 = *(const float4*)&bias[nb + cg * 8 + 4];
#pragma unroll
    for (int r = 0; r < 8; r++) {
        float* op = out + (size_t)(mb + rg * 8 + r) * WORD_V + nb + cg * 8;
        *(float4*)op = make_float4(acc[r][0] + bv0.x, acc[r][1] + bv0.y,
                                   acc[r][2] + bv0.z, acc[r][3] + bv0.w);
        *(float4*)(op + 4) = make_float4(acc[r][4] + bv1.x, acc[r][5] + bv1.y,
                                         acc[r][6] + bv1.z, acc[r][7] + bv1.w);
    }
}

__global__ void k_wnorm(float* __restrict__ wout)
{
    float* p = wout + (size_t)blockIdx.x * WORD_V;
    __shared__ float red[256];
    int tid = threadIdx.x;
    float m = -1e30f;
    for (int k = tid; k < WORD_V; k += 256) m = fmaxf(m, p[k]);
    red[tid] = m; __syncthreads();
    for (int s = 128; s > 0; s >>= 1) { if (tid < s) red[tid] = fmaxf(red[tid], red[tid + s]); __syncthreads(); }
    m = red[0]; __syncthreads();
    float s = 0.f;
    for (int k = tid; k < WORD_V; k += 256) s += expf(p[k] - m);
    red[tid] = s; __syncthreads();
    for (int st = 128; st > 0; st >>= 1) { if (tid < st) red[tid] += red[tid + st]; __syncthreads(); }
    float lse = m + logf(red[0]);
    for (int k = tid; k < WORD_V; k += 256) p[k] -= lse;
}

extern "C" void kernel_launch(void* const* d_in, const int* in_sizes, int n_in,
                              void* d_out, int out_size)
{
    const int*   pos          = (const int*)  d_in[0];
    const int*   word         = (const int*)  d_in[1];
    const float* pos_emb_W    = (const float*)d_in[2];
    const float* word_emb_W   = (const float*)d_in[3];
    const float* w2p_W        = (const float*)d_in[4];
    const float* w2p_b        = (const float*)d_in[5];
    const float* p2w_W        = (const float*)d_in[6];
    const float* p2w_b        = (const float*)d_in[7];
    const float* p_Wih0       = (const float*)d_in[8];
    const float* p_Whh0       = (const float*)d_in[9];
    const float* p_bih0       = (const float*)d_in[10];
    const float* p_bhh0       = (const float*)d_in[11];
    const float* w_Wih0       = (const float*)d_in[12];
    const float* w_Whh0       = (const float*)d_in[13];
    const float* w_bih0       = (const float*)d_in[14];
    const float* w_bhh0       = (const float*)d_in[15];
    const float* w_Wih1       = (const float*)d_in[16];
    const float* w_Whh1       = (const float*)d_in[17];
    const float* w_bih1       = (const float*)d_in[18];
    const float* w_bhh1       = (const float*)d_in[19];
    const float* pos_proj_W   = (const float*)d_in[20];
    const float* pos_proj_b   = (const float*)d_in[21];
    const float* word_proj1_W = (const float*)d_in[22];
    const float* word_proj1_b = (const float*)d_in[23];
    const float* word_proj2_b = (const float*)d_in[24];

    float* pih = nullptr;  cudaGetSymbolAddress((void**)&pih,  g_PIH);
    float* wih = nullptr;  cudaGetSymbolAddress((void**)&wih,  g_WIH0);
    float* wout_dummy;     cudaGetSymbolAddress((void**)&wout_dummy, g_ebuf);

    float* pout = (float*)d_out;
    float* wout = pout + (size_t)TT * 32 * 48;

    // hoisted input projections (token-indexed, independent of recurrence)
    k_pre<<<dim3(8, 16), 256>>>(pos, pos_emb_W, 128, p_Wih0, 1152, 256, pih, 1024);
    k_pre<<<dim3(32, 16), 256>>>(word, word_emb_W, 512, w_Wih0, 768, 1024, wih, 4096);

    // the whole 64-step recurrence in ONE persistent kernel
    k_loop<<<G, 256>>>(w2p_W, w2p_b, p2w_W, p2w_b,
                       p_Wih0, p_Whh0, p_bih0, p_bhh0,
                       w_Wih0, w_Whh0, w_bih0, w_bhh0,
                       w_Wih1, w_Whh1, w_bih1, w_bhh1,
                       pos_proj_W, pos_proj_b, word_proj1_W, word_proj1_b, pout);

    // hoisted logits GEMM + final log-softmax
    k_big<<<dim3(WORD_V / 128, 16), 256>>>(word_emb_W, word_proj2_b, wout);
    k_wnorm<<<TT * 32, 256>>>(wout);
}

// round 6
// speedup vs baseline: 2.2974x; 1.1997x over previous
#include <cuda_runtime.h>
#include <math.h>

#define TT 64
#define WORD_V 32000
#define G 148

typedef unsigned long long ull;

__device__ __align__(16) float g_ph[32 * 256];
__device__ __align__(16) float g_pc[32 * 256];
__device__ __align__(16) float g_wh0[32 * 1024];
__device__ __align__(16) float g_wc0[32 * 1024];
__device__ __align__(16) float g_wh1[32 * 1024];
__device__ __align__(16) float g_wc1[32 * 1024];
__device__ __align__(16) float g_lastw[32 * 1024];
__device__ __align__(16) float g_ebuf[2048 * 512];
__device__ __align__(16) float g_PIH[2048 * 1024];
__device__ __align__(16) float g_WIH0[2048 * 4096];
__device__ __align__(16) float g_pbuf[2097152];
__device__ __align__(16) float g_pbufE[32768];
__device__ unsigned g_cnt;
__device__ volatile unsigned g_gen;

__device__ __forceinline__ void gridbar() {
    __threadfence();
    __syncthreads();
    if (threadIdx.x == 0) {
        unsigned gen = g_gen;
        if (atomicAdd(&g_cnt, 1u) == G - 1) { g_cnt = 0; __threadfence(); g_gen = gen + 1; }
        else { while (g_gen == gen) { } }
    }
    __syncthreads();
}

__device__ __forceinline__ float sigf(float x) { return 1.f / (1.f + expf(-x)); }

__device__ __forceinline__ ull pk2(float lo, float hi) {
    ull r; asm("mov.b64 %0, {%1, %2};" : "=l"(r) : "f"(lo), "f"(hi)); return r;
}
__device__ __forceinline__ void fma2(ull& d, ull a, ull b) {
    asm("fma.rn.f32x2 %0, %1, %2, %3;" : "=l"(d) : "l"(a), "l"(b), "l"(d));
}
__device__ __forceinline__ float2 upk(ull v) {
    float2 f; asm("mov.b64 {%0, %1}, %2;" : "=f"(f.x), "=f"(f.y) : "l"(v)); return f;
}

// ---- stage GEMM: tasks = (32 x 512 col-tile) x split-K; always writes partials ----
// X = concat([Xa|Xb]); W row for global col gc:
//   H>0: row (gc&3)*H+(gc>>2) (gate-interleaved). H==0: gc<ws -> Wa row gc else Wc row gc-ws.
// If xaPart != null, seg0 X[m][c] = tanh(sum_{s<4} xaPart[s*32+m][c] + xaBias[c]).
__device__ __noinline__ void gstage(
    int tid, int cta, float* sX, float* sW,
    int ncolt, int ncols, int ksplit, int kc,
    const float* Xa, int Ka, const float* Wa, int lda, int cba,
    const float* Xb, int Kb, const float* Wb, int ldb, int cbb,
    int H, int ws, const float* Wc,
    float* out, int ostride,
    const float* xaPart, const float* xaBias)
{
    const int rg = tid >> 6, cg = tid & 63;          // 4 row-groups x 64 col-groups
    const int xm = tid & 31, xq = (tid >> 5) & 3;    // sX fill (tid<128)
    const int ntasks = ncolt * ksplit;
    for (int task = cta; task < ntasks; task += G) {
        const int ct = task % ncolt, ks = task / ncolt;
        const int kbeg = ks * kc, kend = kbeg + kc;
        ull acc[8][4];
#pragma unroll
        for (int r = 0; r < 8; r++)
#pragma unroll
            for (int c = 0; c < 4; c++) acc[r][c] = 0ull;
        int base = 0;
#pragma unroll 1
        for (int seg = 0; seg < 2; seg++) {
            const float* Xp = seg ? Xb : Xa;
            const float* Wp = seg ? Wb : Wa;
            const int K = seg ? Kb : Ka, ld = seg ? ldb : lda, cb = seg ? cbb : cba;
            if (K > 0) {
                int lo = kbeg > base ? kbeg : base;
                int hi = kend < base + K ? kend : base + K;
#pragma unroll 1
                for (int k0 = lo; k0 < hi; k0 += 16) {
                    int xo = k0 - base;
                    if (tid < 128) {
                        float4 v;
                        if (seg == 0 && xaPart) {
                            int col0 = xo + xq * 4;
                            float4 s = *(const float4*)&xaBias[col0];
#pragma unroll
                            for (int sp = 0; sp < 4; sp++) {
                                float4 p = __ldcg((const float4*)&xaPart[(size_t)(sp * 32 + xm) * 256 + col0]);
                                s.x += p.x; s.y += p.y; s.z += p.z; s.w += p.w;
                            }
                            v = make_float4(tanhf(s.x), tanhf(s.y), tanhf(s.z), tanhf(s.w));
                        } else {
                            v = __ldcg((const float4*)(Xp + (size_t)xm * K + xo + xq * 4));
                        }
                        sX[(xq * 4 + 0) * 36 + xm] = v.x; sX[(xq * 4 + 1) * 36 + xm] = v.y;
                        sX[(xq * 4 + 2) * 36 + xm] = v.z; sX[(xq * 4 + 3) * 36 + xm] = v.w;
                    }
#pragma unroll
                    for (int i = tid; i < 2048; i += 256) {
                        int c = i & 511, kq = i >> 9;
                        int gc = ct * 512 + c;
                        if (gc >= ncols) gc = ncols - 1;
                        const float* wr;
                        if (H > 0)        wr = Wp + (size_t)((gc & 3) * H + (gc >> 2)) * ld + cb;
                        else if (gc < ws) wr = Wp + (size_t)gc * ld + cb;
                        else              wr = Wc + (size_t)(gc - ws) * ld + cb;
                        float4 v = __ldg((const float4*)(wr + xo + kq * 4));
                        sW[(kq * 4 + 0) * 520 + c] = v.x; sW[(kq * 4 + 1) * 520 + c] = v.y;
                        sW[(kq * 4 + 2) * 520 + c] = v.z; sW[(kq * 4 + 3) * 520 + c] = v.w;
                    }
                    __syncthreads();
#pragma unroll
                    for (int k = 0; k < 16; k++) {
                        const float* xr = &sX[k * 36 + rg * 8];
                        float4 a0 = *(const float4*)xr, a1 = *(const float4*)(xr + 4);
                        const float* br = &sW[k * 520 + cg * 8];
                        float4 b0 = *(const float4*)br, b1 = *(const float4*)(br + 4);
                        ull bp0 = pk2(b0.x, b0.y), bp1 = pk2(b0.z, b0.w);
                        ull bp2 = pk2(b1.x, b1.y), bp3 = pk2(b1.z, b1.w);
                        float av[8] = {a0.x, a0.y, a0.z, a0.w, a1.x, a1.y, a1.z, a1.w};
#pragma unroll
                        for (int r = 0; r < 8; r++) {
                            ull ad = pk2(av[r], av[r]);
                            fma2(acc[r][0], ad, bp0);
                            fma2(acc[r][1], ad, bp1);
                            fma2(acc[r][2], ad, bp2);
                            fma2(acc[r][3], ad, bp3);
                        }
                    }
                    __syncthreads();
                }
            }
            base += K;
        }
        int oc = ct * 512 + cg * 8;
        if (oc < ncols) {
#pragma unroll
            for (int r = 0; r < 8; r++) {
                float2 p0 = upk(acc[r][0]), p1 = upk(acc[r][1]);
                float2 p2 = upk(acc[r][2]), p3 = upk(acc[r][3]);
                float* op = &out[(size_t)(ks * 32 + rg * 8 + r) * ostride + oc];
                *(float4*)op = make_float4(p0.x, p0.y, p1.x, p1.y);
                *(float4*)(op + 4) = make_float4(p2.x, p2.y, p3.x, p3.y);
            }
        }
    }
}

__global__ void __launch_bounds__(256, 1) k_loop(
    const float* __restrict__ w2p_W, const float* __restrict__ w2p_b,
    const float* __restrict__ p2w_W, const float* __restrict__ p2w_b,
    const float* __restrict__ p_Wih0, const float* __restrict__ p_Whh0,
    const float* __restrict__ p_bih0, const float* __restrict__ p_bhh0,
    const float* __restrict__ w_Wih0, const float* __restrict__ w_Whh0,
    const float* __restrict__ w_bih0, const float* __restrict__ w_bhh0,
    const float* __restrict__ w_Wih1, const float* __restrict__ w_Whh1,
    const float* __restrict__ w_bih1, const float* __restrict__ w_bhh1,
    const float* __restrict__ pos_proj_W, const float* __restrict__ pos_proj_b,
    const float* __restrict__ word_proj1_W, const float* __restrict__ word_proj1_b,
    float* __restrict__ pout)
{
    __shared__ float sX[16 * 36];
    __shared__ float sW[16 * 520];
    const int tid = threadIdx.x, cta = blockIdx.x;
    const int gt = cta * 256 + tid;

    { // zero states
        float4 z = make_float4(0.f, 0.f, 0.f, 0.f);
        if (gt < 2048) { ((float4*)g_ph)[gt] = z; ((float4*)g_pc)[gt] = z; }
        if (gt < 8192) { ((float4*)g_wh0)[gt] = z; ((float4*)g_wc0)[gt] = z;
                         ((float4*)g_wh1)[gt] = z; ((float4*)g_wc1)[gt] = z; }
    }
    gridbar();

    for (int t = 0; t <= TT; t++) {
        // A: pbuf = wh1 @ [w2p_W | word_proj1_W]^T  (1536 cols, K=1024, split-16)
        gstage(tid, cta, sX, sW, 3, 1536, 16, 64,
               g_wh1, 1024, w2p_W, 1024, 0,
               nullptr, 0, nullptr, 0, 0,
               0, 1024, word_proj1_W, g_pbuf, 1536, nullptr, nullptr);
        gridbar();
        // B: lastw = tanh(sum+b);  e_{t-1} = sum+b
        for (int gid = gt; gid < 12288; gid += G * 256) {
            if (gid < 8192) {
                int m = gid >> 8, cq = gid & 255;
                float4 s = *(const float4*)&w2p_b[cq * 4];
#pragma unroll
                for (int ks = 0; ks < 16; ks++) {
                    float4 p = __ldcg((const float4*)&g_pbuf[(size_t)(ks * 32 + m) * 1536 + cq * 4]);
                    s.x += p.x; s.y += p.y; s.z += p.z; s.w += p.w;
                }
                *(float4*)&g_lastw[m * 1024 + cq * 4] =
                    make_float4(tanhf(s.x), tanhf(s.y), tanhf(s.z), tanhf(s.w));
            } else if (t >= 1) {
                int i2 = gid - 8192, m = i2 >> 7, cq = i2 & 127;
                float4 s = *(const float4*)&word_proj1_b[cq * 4];
#pragma unroll
                for (int ks = 0; ks < 16; ks++) {
                    float4 p = __ldcg((const float4*)&g_pbuf[(size_t)(ks * 32 + m) * 1536 + 1024 + cq * 4]);
                    s.x += p.x; s.y += p.y; s.z += p.z; s.w += p.w;
                }
                *(float4*)&g_ebuf[(size_t)((t - 1) * 32 + m) * 512 + cq * 4] = s;
            }
        }
        if (t == TT) break;
        gridbar();
        // C: pos gates (K = lastw 1024 + ph 256), 1024 cols, split-40
        gstage(tid, cta, sX, sW, 2, 1024, 40, 32,
               g_lastw, 1024, p_Wih0, 1152, 128,
               g_ph, 256, p_Whh0, 256, 0,
               256, 0, nullptr, g_pbuf, 1024, nullptr, nullptr);
        gridbar();
        // D: pos cell update
        for (int gid = gt; gid < 8192; gid += G * 256) {
            int m = gid >> 8, u = gid & 255;
            float4 s = __ldg((const float4*)&g_PIH[(size_t)(t * 32 + m) * 1024 + u * 4]);
#pragma unroll
            for (int ks = 0; ks < 40; ks++) {
                float4 p = __ldcg((const float4*)&g_pbuf[(size_t)(ks * 32 + m) * 1024 + u * 4]);
                s.x += p.x; s.y += p.y; s.z += p.z; s.w += p.w;
            }
            float iv = sigf(s.x + __ldg(&p_bih0[u]) + __ldg(&p_bhh0[u]));
            float fv = sigf(s.y + __ldg(&p_bih0[256 + u]) + __ldg(&p_bhh0[256 + u]));
            float gv = tanhf(s.z + __ldg(&p_bih0[512 + u]) + __ldg(&p_bhh0[512 + u]));
            float ov = sigf(s.w + __ldg(&p_bih0[768 + u]) + __ldg(&p_bhh0[768 + u]));
            float c = fv * __ldcg(&g_pc[gid]) + iv * gv;
            g_pc[gid] = c; g_ph[gid] = ov * tanhf(c);
        }
        gridbar();
        // E: lastp partials (CTAs 0-3, K=256 split-4) + pos logits (CTAs 4-35)
        gstage(tid, cta, sX, sW, 1, 256, 4, 64,
               g_ph, 256, p2w_W, 256, 0,
               nullptr, 0, nullptr, 0, 0,
               0, 1 << 30, nullptr, g_pbufE, 256, nullptr, nullptr);
        if (cta >= 4 && cta < 36) {
            int r = cta - 4;
            float v = 0.f;
            if (tid < 48) {
                v = __ldg(&pos_proj_b[tid]);
                const float4* xp = (const float4*)(g_ph + r * 256);
                const float4* wp = (const float4*)(pos_proj_W + tid * 256);
#pragma unroll 8
                for (int k = 0; k < 64; k++) {
                    float4 x = __ldcg(xp + k), w = __ldg(wp + k);
                    v = fmaf(x.x, w.x, v); v = fmaf(x.y, w.y, v);
                    v = fmaf(x.z, w.z, v); v = fmaf(x.w, w.w, v);
                }
                sW[tid] = v;
            }
            __syncthreads();
            if (tid == 0) {
                float mx = -1e30f;
                for (int k = 0; k < 48; k++) mx = fmaxf(mx, sW[k]);
                float sm = 0.f;
                for (int k = 0; k < 48; k++) sm += expf(sW[k] - mx);
                sW[48] = mx + logf(sm);
            }
            __syncthreads();
            if (tid < 48) pout[((size_t)t * 32 + r) * 48 + tid] = v - sW[48];
        }
        gridbar();
        // F: word LSTM0 gates (K = lastp 256 (fused from pbufE) + wh0 1024), split-16
        gstage(tid, cta, sX, sW, 8, 4096, 16, 80,
               nullptr, 256, w_Wih0, 768, 512,
               g_wh0, 1024, w_Whh0, 1024, 0,
               1024, 0, nullptr, g_pbuf, 4096, g_pbufE, p2w_b);
        gridbar();
        // G: word LSTM0 cell
        for (int gid = gt; gid < 32768; gid += G * 256) {
            int m = gid >> 10, u = gid & 1023;
            float4 s = __ldg((const float4*)&g_WIH0[(size_t)(t * 32 + m) * 4096 + u * 4]);
#pragma unroll
            for (int ks = 0; ks < 16; ks++) {
                float4 p = __ldcg((const float4*)&g_pbuf[(size_t)(ks * 32 + m) * 4096 + u * 4]);
                s.x += p.x; s.y += p.y; s.z += p.z; s.w += p.w;
            }
            float iv = sigf(s.x + __ldg(&w_bih0[u]) + __ldg(&w_bhh0[u]));
            float fv = sigf(s.y + __ldg(&w_bih0[1024 + u]) + __ldg(&w_bhh0[1024 + u]));
            float gv = tanhf(s.z + __ldg(&w_bih0[2048 + u]) + __ldg(&w_bhh0[2048 + u]));
            float ov = sigf(s.w + __ldg(&w_bih0[3072 + u]) + __ldg(&w_bhh0[3072 + u]));
            float c = fv * __ldcg(&g_wc0[gid]) + iv * gv;
            g_wc0[gid] = c; g_wh0[gid] = ov * tanhf(c);
        }
        gridbar();
        // H: word LSTM1 gates (K = wh0 1024 + wh1 1024), split-16
        gstage(tid, cta, sX, sW, 8, 4096, 16, 128,
               g_wh0, 1024, w_Wih1, 1024, 0,
               g_wh1, 1024, w_Whh1, 1024, 0,
               1024, 0, nullptr, g_pbuf, 4096, nullptr, nullptr);
        gridbar();
        // I: word LSTM1 cell
        for (int gid = gt; gid < 32768; gid += G * 256) {
            int m = gid >> 10, u = gid & 1023;
            float4 s = make_float4(0.f, 0.f, 0.f, 0.f);
#pragma unroll
            for (int ks = 0; ks < 16; ks++) {
                float4 p = __ldcg((const float4*)&g_pbuf[(size_t)(ks * 32 + m) * 4096 + u * 4]);
                s.x += p.x; s.y += p.y; s.z += p.z; s.w += p.w;
            }
            float iv = sigf(s.x + __ldg(&w_bih1[u]) + __ldg(&w_bhh1[u]));
            float fv = sigf(s.y + __ldg(&w_bih1[1024 + u]) + __ldg(&w_bhh1[1024 + u]));
            float gv = tanhf(s.z + __ldg(&w_bih1[2048 + u]) + __ldg(&w_bhh1[2048 + u]));
            float ov = sigf(s.w + __ldg(&w_bih1[3072 + u]) + __ldg(&w_bhh1[3072 + u]));
            float c = fv * __ldcg(&g_wc1[gid]) + iv * gv;
            g_wc1[gid] = c; g_wh1[gid] = ov * tanhf(c);
        }
        gridbar();
    }
}

// ---- shared inner for 64x128-tile f32x2 GEMMs (k_pre / k_big) ----
struct Acc88 { ull a[8][4]; };

__device__ __forceinline__ void mm_inner(float (*As)[68], float (*Bs)[132],
                                         int rg, int cg, Acc88& A)
{
#pragma unroll
    for (int k = 0; k < 16; k++) {
        const float* xr = &As[k][rg * 8];
        float4 a0 = *(const float4*)xr, a1 = *(const float4*)(xr + 4);
        const float* br = &Bs[k][cg * 8];
        float4 b0 = *(const float4*)br, b1 = *(const float4*)(br + 4);
        ull bp0 = pk2(b0.x, b0.y), bp1 = pk2(b0.z, b0.w);
        ull bp2 = pk2(b1.x, b1.y), bp3 = pk2(b1.z, b1.w);
        float av[8] = {a0.x, a0.y, a0.z, a0.w, a1.x, a1.y, a1.z, a1.w};
#pragma unroll
        for (int r = 0; r < 8; r++) {
            ull ad = pk2(av[r], av[r]);
            fma2(A.a[r][0], ad, bp0);
            fma2(A.a[r][1], ad, bp1);
            fma2(A.a[r][2], ad, bp2);
            fma2(A.a[r][3], ad, bp3);
        }
    }
}

// precompute: out[2048][N] = table[idx[m]] @ Wrow^T (gate-interleaved rows)
__global__ void __launch_bounds__(128, 4) k_pre(
    const int* __restrict__ idx, const float* __restrict__ table, int K,
    const float* __restrict__ W, int ldW, int H, float* __restrict__ out, int N)
{
    __shared__ float As[16][68];
    __shared__ float Bs[16][132];
    __shared__ const float* rp[64];
    int tid = threadIdx.x;
    int mb = blockIdx.y * 64, nb = blockIdx.x * 128;
    if (tid < 64) rp[tid] = table + (size_t)idx[mb + tid] * K;
    __syncthreads();
    Acc88 A;
#pragma unroll
    for (int r = 0; r < 8; r++)
#pragma unroll
        for (int c = 0; c < 4; c++) A.a[r][c] = 0ull;
    int rg = tid >> 4, cg = tid & 15;
    for (int k0 = 0; k0 < K; k0 += 16) {
#pragma unroll
        for (int i = tid; i < 256; i += 128) {
            int m = i & 63, kq = i >> 6;
            float4 v = *(const float4*)(rp[m] + k0 + kq * 4);
            As[kq * 4 + 0][m] = v.x; As[kq * 4 + 1][m] = v.y;
            As[kq * 4 + 2][m] = v.z; As[kq * 4 + 3][m] = v.w;
        }
#pragma unroll
        for (int i = tid; i < 512; i += 128) {
            int c = i & 127, kq = i >> 7;
            int gc = nb + c;
            float4 v = __ldg((const float4*)(W + (size_t)((gc & 3) * H + (gc >> 2)) * ldW + k0 + kq * 4));
            Bs[kq * 4 + 0][c] = v.x; Bs[kq * 4 + 1][c] = v.y;
            Bs[kq * 4 + 2][c] = v.z; Bs[kq * 4 + 3][c] = v.w;
        }
        __syncthreads();
        mm_inner(As, Bs, rg, cg, A);
        __syncthreads();
    }
#pragma unroll
    for (int r = 0; r < 8; r++) {
        float2 p0 = upk(A.a[r][0]), p1 = upk(A.a[r][1]);
        float2 p2 = upk(A.a[r][2]), p3 = upk(A.a[r][3]);
        float* op = out + (size_t)(mb + rg * 8 + r) * N + nb + cg * 8;
        *(float4*)op = make_float4(p0.x, p0.y, p1.x, p1.y);
        *(float4*)(op + 4) = make_float4(p2.x, p2.y, p3.x, p3.y);
    }
}

// big logits GEMM: wout[2048,32000] = E @ word_emb^T + b
__global__ void __launch_bounds__(128, 4) k_big(
    const float* __restrict__ W, const float* __restrict__ bias, float* __restrict__ out)
{
    __shared__ float As[16][68];
    __shared__ float Bs[16][132];
    int tid = threadIdx.x;
    int mb = blockIdx.y * 64, nb = blockIdx.x * 128;
    Acc88 A;
#pragma unroll
    for (int r = 0; r < 8; r++)
#pragma unroll
        for (int c = 0; c < 4; c++) A.a[r][c] = 0ull;
    int rg = tid >> 4, cg = tid & 15;
    for (int k0 = 0; k0 < 512; k0 += 16) {
#pragma unroll
        for (int i = tid; i < 256; i += 128) {
            int m = i & 63, kq = i >> 6;
            float4 v = *(const float4*)(g_ebuf + (size_t)(mb + m) * 512 + k0 + kq * 4);
            As[kq * 4 + 0][m] = v.x; As[kq * 4 + 1][m] = v.y;
            As[kq * 4 + 2][m] = v.z; As[kq * 4 + 3][m] = v.w;
        }
#pragma unroll
        for (int i = tid; i < 512; i += 128) {
            int c = i & 127, kq = i >> 7;
            float4 v = __ldg((const float4*)(W + (size_t)(nb + c) * 512 + k0 + kq * 4));
            Bs[kq * 4 + 0][c] = v.x; Bs[kq * 4 + 1][c] = v.y;
            Bs[kq * 4 + 2][c] = v.z; Bs[kq * 4 + 3][c] = v.w;
        }
        __syncthreads();
        mm_inner(As, Bs, rg, cg, A);
        __syncthreads();
    }
    float4 bv0 = *(const float4*)&bias[nb + cg * 8];
    float4 bv1 = *(const float4*)&bias[nb + cg * 8 + 4];
#pragma unroll
    for (int r = 0; r < 8; r++) {
        float2 p0 = upk(A.a[r][0]), p1 = upk(A.a[r][1]);
        float2 p2 = upk(A.a[r][2]), p3 = upk(A.a[r][3]);
        float* op = out + (size_t)(mb + rg * 8 + r) * WORD_V + nb + cg * 8;
        *(float4*)op = make_float4(p0.x + bv0.x, p0.y + bv0.y, p1.x + bv0.z, p1.y + bv0.w);
        *(float4*)(op + 4) = make_float4(p2.x + bv1.x, p2.y + bv1.y, p3.x + bv1.z, p3.y + bv1.w);
    }
}

__global__ void k_wnorm(float* __restrict__ wout)
{
    float* p = wout + (size_t)blockIdx.x * WORD_V;
    __shared__ float red[256];
    int tid = threadIdx.x;
    float m = -1e30f;
    for (int k = tid; k < WORD_V; k += 256) m = fmaxf(m, p[k]);
    red[tid] = m; __syncthreads();
    for (int s = 128; s > 0; s >>= 1) { if (tid < s) red[tid] = fmaxf(red[tid], red[tid + s]); __syncthreads(); }
    m = red[0]; __syncthreads();
    float s = 0.f;
    for (int k = tid; k < WORD_V; k += 256) s += expf(p[k] - m);
    red[tid] = s; __syncthreads();
    for (int st = 128; st > 0; st >>= 1) { if (tid < st) red[tid] += red[tid + st]; __syncthreads(); }
    float lse = m + logf(red[0]);
    for (int k = tid; k < WORD_V; k += 256) p[k] -= lse;
}

extern "C" void kernel_launch(void* const* d_in, const int* in_sizes, int n_in,
                              void* d_out, int out_size)
{
    const int*   pos          = (const int*)  d_in[0];
    const int*   word         = (const int*)  d_in[1];
    const float* pos_emb_W    = (const float*)d_in[2];
    const float* word_emb_W   = (const float*)d_in[3];
    const float* w2p_W        = (const float*)d_in[4];
    const float* w2p_b        = (const float*)d_in[5];
    const float* p2w_W        = (const float*)d_in[6];
    const float* p2w_b        = (const float*)d_in[7];
    const float* p_Wih0       = (const float*)d_in[8];
    const float* p_Whh0       = (const float*)d_in[9];
    const float* p_bih0       = (const float*)d_in[10];
    const float* p_bhh0       = (const float*)d_in[11];
    const float* w_Wih0       = (const float*)d_in[12];
    const float* w_Whh0       = (const float*)d_in[13];
    const float* w_bih0       = (const float*)d_in[14];
    const float* w_bhh0       = (const float*)d_in[15];
    const float* w_Wih1       = (const float*)d_in[16];
    const float* w_Whh1       = (const float*)d_in[17];
    const float* w_bih1       = (const float*)d_in[18];
    const float* w_bhh1       = (const float*)d_in[19];
    const float* pos_proj_W   = (const float*)d_in[20];
    const float* pos_proj_b   = (const float*)d_in[21];
    const float* word_proj1_W = (const float*)d_in[22];
    const float* word_proj1_b = (const float*)d_in[23];
    const float* word_proj2_b = (const float*)d_in[24];

    float* pih = nullptr;  cudaGetSymbolAddress((void**)&pih,  g_PIH);
    float* wih = nullptr;  cudaGetSymbolAddress((void**)&wih,  g_WIH0);

    float* pout = (float*)d_out;
    float* wout = pout + (size_t)TT * 32 * 48;

    // hoisted input projections (token-indexed, independent of recurrence)
    k_pre<<<dim3(8, 32), 128>>>(pos, pos_emb_W, 128, p_Wih0, 1152, 256, pih, 1024);
    k_pre<<<dim3(32, 32), 128>>>(word, word_emb_W, 512, w_Wih0, 768, 1024, wih, 4096);

    // the whole 64-step recurrence in ONE persistent kernel
    k_loop<<<G, 256>>>(w2p_W, w2p_b, p2w_W, p2w_b,
                       p_Wih0, p_Whh0, p_bih0, p_bhh0,
                       w_Wih0, w_Whh0, w_bih0, w_bhh0,
                       w_Wih1, w_Whh1, w_bih1, w_bhh1,
                       pos_proj_W, pos_proj_b, word_proj1_W, word_proj1_b, pout);

    // hoisted logits GEMM + final log-softmax
    k_big<<<dim3(WORD_V / 128, 32), 128>>>(word_emb_W, word_proj2_b, wout);
    k_wnorm<<<TT * 32, 256>>>(wout);
}

// round 8
// speedup vs baseline: 2.3531x; 1.0242x over previous
#include <cuda_runtime.h>
#include <math.h>

#define TT 64
#define WORD_V 32000
#define G 148

typedef unsigned long long ull;

__device__ __align__(16) float g_ph[32 * 256];
__device__ __align__(16) float g_pc[32 * 256];
__device__ __align__(16) float g_wh0[32 * 1024];
__device__ __align__(16) float g_wc0[32 * 1024];
__device__ __align__(16) float g_wh1[32 * 1024];
__device__ __align__(16) float g_wc1[32 * 1024];
__device__ __align__(16) float g_ebuf[2048 * 512];
__device__ __align__(16) float g_PIH[2048 * 1024];
__device__ __align__(16) float g_WIH0[2048 * 4096];
__device__ __align__(16) float g_pbuf[2097152];
__device__ __align__(16) float g_pbufE[32768];
__device__ unsigned g_cnt;
__device__ volatile unsigned g_gen;

#define PBUF_C 786432   // stage-C partial region offset inside g_pbuf

__device__ __forceinline__ void gridbar() {
    __threadfence();
    __syncthreads();
    if (threadIdx.x == 0) {
        unsigned gen = g_gen;
        if (atomicAdd(&g_cnt, 1u) == G - 1) { g_cnt = 0; __threadfence(); g_gen = gen + 1; }
        else { while (g_gen == gen) { } }
    }
    __syncthreads();
}

__device__ __forceinline__ float sigf(float x) { return 1.f / (1.f + expf(-x)); }

__device__ __forceinline__ ull pk2(float lo, float hi) {
    ull r; asm("mov.b64 %0, {%1, %2};" : "=l"(r) : "f"(lo), "f"(hi)); return r;
}
__device__ __forceinline__ void fma2(ull& d, ull a, ull b) {
    asm("fma.rn.f32x2 %0, %1, %2, %3;" : "=l"(d) : "l"(a), "l"(b), "l"(d));
}
__device__ __forceinline__ float2 upk(ull v) {
    float2 f; asm("mov.b64 {%0, %1}, %2;" : "=f"(f.x), "=f"(f.y) : "l"(v)); return f;
}
__device__ __forceinline__ unsigned cvt_tf32(float f) {
    unsigned u; asm("cvt.rna.tf32.f32 %0, %1;" : "=r"(u) : "f"(f)); return u;
}
__device__ __forceinline__ void mma_tf32(float* d, uint4 a, uint2 b) {
    asm("mma.sync.aligned.m16n8k8.row.col.f32.tf32.tf32.f32 "
        "{%0,%1,%2,%3}, {%4,%5,%6,%7}, {%8,%9}, {%0,%1,%2,%3};"
        : "+f"(d[0]), "+f"(d[1]), "+f"(d[2]), "+f"(d[3])
        : "r"(a.x), "r"(a.y), "r"(a.z), "r"(a.w), "r"(b.x), "r"(b.y));
}

// ---- stage GEMM: tasks = (32 x 512 col-tile) x split-K; writes partials ----
// If xaPart != null, seg0 X[m][c] = tanh(sum_{s<xaNs} xaPart[(s*32+m)*xaStride + c] + xaBias[c]).
__device__ __noinline__ void gstage(
    int tid, int cta, float* sX, float* sW,
    int ncolt, int ncols, int ksplit, int kc,
    const float* Xa, int Ka, const float* Wa, int lda, int cba,
    const float* Xb, int Kb, const float* Wb, int ldb, int cbb,
    int H, int ws, const float* Wc,
    float* out, int ostride,
    const float* xaPart, const float* xaBias, int xaNs, int xaStride)
{
    const int rg = tid >> 6, cg = tid & 63;
    const int xm = tid & 31, xq = (tid >> 5) & 3;
    const int ntasks = ncolt * ksplit;
    for (int task = cta; task < ntasks; task += G) {
        const int ct = task % ncolt, ks = task / ncolt;
        const int kbeg = ks * kc, kend = kbeg + kc;
        ull acc[8][4];
#pragma unroll
        for (int r = 0; r < 8; r++)
#pragma unroll
            for (int c = 0; c < 4; c++) acc[r][c] = 0ull;
        int base = 0;
#pragma unroll 1
        for (int seg = 0; seg < 2; seg++) {
            const float* Xp = seg ? Xb : Xa;
            const float* Wp = seg ? Wb : Wa;
            const int K = seg ? Kb : Ka, ld = seg ? ldb : lda, cb = seg ? cbb : cba;
            if (K > 0) {
                int lo = kbeg > base ? kbeg : base;
                int hi = kend < base + K ? kend : base + K;
#pragma unroll 1
                for (int k0 = lo; k0 < hi; k0 += 16) {
                    int xo = k0 - base;
                    if (tid < 128) {
                        float4 v;
                        if (seg == 0 && xaPart) {
                            int col0 = xo + xq * 4;
                            float4 s = *(const float4*)&xaBias[col0];
                            for (int sp = 0; sp < xaNs; sp++) {
                                float4 p = __ldcg((const float4*)&xaPart[(size_t)(sp * 32 + xm) * xaStride + col0]);
                                s.x += p.x; s.y += p.y; s.z += p.z; s.w += p.w;
                            }
                            v = make_float4(tanhf(s.x), tanhf(s.y), tanhf(s.z), tanhf(s.w));
                        } else {
                            v = __ldcg((const float4*)(Xp + (size_t)xm * K + xo + xq * 4));
                        }
                        sX[(xq * 4 + 0) * 36 + xm] = v.x; sX[(xq * 4 + 1) * 36 + xm] = v.y;
                        sX[(xq * 4 + 2) * 36 + xm] = v.z; sX[(xq * 4 + 3) * 36 + xm] = v.w;
                    }
#pragma unroll
                    for (int i = tid; i < 2048; i += 256) {
                        int c = i & 511, kq = i >> 9;
                        int gc = ct * 512 + c;
                        if (gc >= ncols) gc = ncols - 1;
                        const float* wr;
                        if (H > 0)        wr = Wp + (size_t)((gc & 3) * H + (gc >> 2)) * ld + cb;
                        else if (gc < ws) wr = Wp + (size_t)gc * ld + cb;
                        else              wr = Wc + (size_t)(gc - ws) * ld + cb;
                        float4 v = __ldg((const float4*)(wr + xo + kq * 4));
                        sW[(kq * 4 + 0) * 520 + c] = v.x; sW[(kq * 4 + 1) * 520 + c] = v.y;
                        sW[(kq * 4 + 2) * 520 + c] = v.z; sW[(kq * 4 + 3) * 520 + c] = v.w;
                    }
                    __syncthreads();
#pragma unroll
                    for (int k = 0; k < 16; k++) {
                        const float* xr = &sX[k * 36 + rg * 8];
                        float4 a0 = *(const float4*)xr, a1 = *(const float4*)(xr + 4);
                        const float* br = &sW[k * 520 + cg * 8];
                        float4 b0 = *(const float4*)br, b1 = *(const float4*)(br + 4);
                        ull bp0 = pk2(b0.x, b0.y), bp1 = pk2(b0.z, b0.w);
                        ull bp2 = pk2(b1.x, b1.y), bp3 = pk2(b1.z, b1.w);
                        float av[8] = {a0.x, a0.y, a0.z, a0.w, a1.x, a1.y, a1.z, a1.w};
#pragma unroll
                        for (int r = 0; r < 8; r++) {
                            ull ad = pk2(av[r], av[r]);
                            fma2(acc[r][0], ad, bp0);
                            fma2(acc[r][1], ad, bp1);
                            fma2(acc[r][2], ad, bp2);
                            fma2(acc[r][3], ad, bp3);
                        }
                    }
                    __syncthreads();
                }
            }
            base += K;
        }
        int oc = ct * 512 + cg * 8;
        if (oc < ncols) {
#pragma unroll
            for (int r = 0; r < 8; r++) {
                float2 p0 = upk(acc[r][0]), p1 = upk(acc[r][1]);
                float2 p2 = upk(acc[r][2]), p3 = upk(acc[r][3]);
                float* op = &out[(size_t)(ks * 32 + rg * 8 + r) * ostride + oc];
                *(float4*)op = make_float4(p0.x, p0.y, p1.x, p1.y);
                *(float4*)(op + 4) = make_float4(p2.x, p2.y, p3.x, p3.y);
            }
        }
    }
}

__global__ void __launch_bounds__(256, 1) k_loop(
    const float* __restrict__ w2p_W, const float* __restrict__ w2p_b,
    const float* __restrict__ p2w_W, const float* __restrict__ p2w_b,
    const float* __restrict__ p_Wih0, const float* __restrict__ p_Whh0,
    const float* __restrict__ p_bih0, const float* __restrict__ p_bhh0,
    const float* __restrict__ w_Wih0, const float* __restrict__ w_Whh0,
    const float* __restrict__ w_bih0, const float* __restrict__ w_bhh0,
    const float* __restrict__ w_Wih1, const float* __restrict__ w_Whh1,
    const float* __restrict__ w_bih1, const float* __restrict__ w_bhh1,
    const float* __restrict__ pos_proj_W, const float* __restrict__ pos_proj_b,
    const float* __restrict__ word_proj1_W, const float* __restrict__ word_proj1_b,
    float* __restrict__ pout)
{
    __shared__ float sX[16 * 36];
    __shared__ float sW[16 * 520];
    const int tid = threadIdx.x, cta = blockIdx.x;
    const int gt = cta * 256 + tid;

    { // zero states
        float4 z = make_float4(0.f, 0.f, 0.f, 0.f);
        if (gt < 2048) { ((float4*)g_ph)[gt] = z; ((float4*)g_pc)[gt] = z; }
        if (gt < 8192) { ((float4*)g_wh0)[gt] = z; ((float4*)g_wc0)[gt] = z;
                         ((float4*)g_wh1)[gt] = z; ((float4*)g_wc1)[gt] = z; }
    }
    gridbar();

    for (int t = 0; t <= TT; t++) {
        // A: pbuf = wh1 @ [w2p_W | word_proj1_W]^T  (1536 cols, K=1024, split-16)
        gstage(tid, cta, sX, sW, 3, 1536, 16, 64,
               g_wh1, 1024, w2p_W, 1024, 0,
               nullptr, 0, nullptr, 0, 0,
               0, 1024, word_proj1_W, g_pbuf, 1536, nullptr, nullptr, 0, 0);
        gridbar();
        if (t == TT) {   // final ebuf reduce (for t-1) with all CTAs, then done
            for (int idx = gt; idx < 4096; idx += G * 256) {
                int m = idx >> 7, cq = idx & 127;
                float4 s = *(const float4*)&word_proj1_b[cq * 4];
#pragma unroll
                for (int ks = 0; ks < 16; ks++) {
                    float4 p = __ldcg((const float4*)&g_pbuf[(size_t)(ks * 32 + m) * 1536 + 1024 + cq * 4]);
                    s.x += p.x; s.y += p.y; s.z += p.z; s.w += p.w;
                }
                *(float4*)&g_ebuf[(size_t)((t - 1) * 32 + m) * 512 + cq * 4] = s;
            }
            break;
        }
        // C: pos gates (K = lastw 1024 fused-from-partials + ph 256), 80 tasks;
        //    spare CTAs reduce ebuf_{t-1} from pbuf cols 1024-1535.
        gstage(tid, cta, sX, sW, 2, 1024, 40, 32,
               nullptr, 1024, p_Wih0, 1152, 128,
               g_ph, 256, p_Whh0, 256, 0,
               256, 0, nullptr, g_pbuf + PBUF_C, 1024, g_pbuf, w2p_b, 16, 1536);
        if (cta >= 80 && t >= 1) {
            for (int idx = (cta - 80) * 256 + tid; idx < 4096; idx += 68 * 256) {
                int m = idx >> 7, cq = idx & 127;
                float4 s = *(const float4*)&word_proj1_b[cq * 4];
#pragma unroll
                for (int ks = 0; ks < 16; ks++) {
                    float4 p = __ldcg((const float4*)&g_pbuf[(size_t)(ks * 32 + m) * 1536 + 1024 + cq * 4]);
                    s.x += p.x; s.y += p.y; s.z += p.z; s.w += p.w;
                }
                *(float4*)&g_ebuf[(size_t)((t - 1) * 32 + m) * 512 + cq * 4] = s;
            }
        }
        gridbar();
        // D: pos cell update (partials at PBUF_C)
        for (int gid = gt; gid < 8192; gid += G * 256) {
            int m = gid >> 8, u = gid & 255;
            float4 s = __ldg((const float4*)&g_PIH[(size_t)(t * 32 + m) * 1024 + u * 4]);
#pragma unroll
            for (int ks = 0; ks < 40; ks++) {
                float4 p = __ldcg((const float4*)&g_pbuf[PBUF_C + (size_t)(ks * 32 + m) * 1024 + u * 4]);
                s.x += p.x; s.y += p.y; s.z += p.z; s.w += p.w;
            }
            float iv = sigf(s.x + __ldg(&p_bih0[u]) + __ldg(&p_bhh0[u]));
            float fv = sigf(s.y + __ldg(&p_bih0[256 + u]) + __ldg(&p_bhh0[256 + u]));
            float gv = tanhf(s.z + __ldg(&p_bih0[512 + u]) + __ldg(&p_bhh0[512 + u]));
            float ov = sigf(s.w + __ldg(&p_bih0[768 + u]) + __ldg(&p_bhh0[768 + u]));
            float c = fv * __ldcg(&g_pc[gid]) + iv * gv;
            g_pc[gid] = c; g_ph[gid] = ov * tanhf(c);
        }
        gridbar();
        // E: lastp partials (CTAs 0-3) + pos logits (CTAs 4-35)
        gstage(tid, cta, sX, sW, 1, 256, 4, 64,
               g_ph, 256, p2w_W, 256, 0,
               nullptr, 0, nullptr, 0, 0,
               0, 1 << 30, nullptr, g_pbufE, 256, nullptr, nullptr, 0, 0);
        if (cta >= 4 && cta < 36) {
            int r = cta - 4;
            float v = 0.f;
            if (tid < 48) {
                v = __ldg(&pos_proj_b[tid]);
                const float4* xp = (const float4*)(g_ph + r * 256);
                const float4* wp = (const float4*)(pos_proj_W + tid * 256);
#pragma unroll 8
                for (int k = 0; k < 64; k++) {
                    float4 x = __ldcg(xp + k), w = __ldg(wp + k);
                    v = fmaf(x.x, w.x, v); v = fmaf(x.y, w.y, v);
                    v = fmaf(x.z, w.z, v); v = fmaf(x.w, w.w, v);
                }
                sW[tid] = v;
            }
            __syncthreads();
            if (tid == 0) {
                float mx = -1e30f;
                for (int k = 0; k < 48; k++) mx = fmaxf(mx, sW[k]);
                float sm = 0.f;
                for (int k = 0; k < 48; k++) sm += expf(sW[k] - mx);
                sW[48] = mx + logf(sm);
            }
            __syncthreads();
            if (tid < 48) pout[((size_t)t * 32 + r) * 48 + tid] = v - sW[48];
        }
        gridbar();
        // F: word LSTM0 gates (K = lastp 256 fused + wh0 1024), split-16
        gstage(tid, cta, sX, sW, 8, 4096, 16, 80,
               nullptr, 256, w_Wih0, 768, 512,
               g_wh0, 1024, w_Whh0, 1024, 0,
               1024, 0, nullptr, g_pbuf, 4096, g_pbufE, p2w_b, 4, 256);
        gridbar();
        // G: word LSTM0 cell
        for (int gid = gt; gid < 32768; gid += G * 256) {
            int m = gid >> 10, u = gid & 1023;
            float4 s = __ldg((const float4*)&g_WIH0[(size_t)(t * 32 + m) * 4096 + u * 4]);
#pragma unroll
            for (int ks = 0; ks < 16; ks++) {
                float4 p = __ldcg((const float4*)&g_pbuf[(size_t)(ks * 32 + m) * 4096 + u * 4]);
                s.x += p.x; s.y += p.y; s.z += p.z; s.w += p.w;
            }
            float iv = sigf(s.x + __ldg(&w_bih0[u]) + __ldg(&w_bhh0[u]));
            float fv = sigf(s.y + __ldg(&w_bih0[1024 + u]) + __ldg(&w_bhh0[1024 + u]));
            float gv = tanhf(s.z + __ldg(&w_bih0[2048 + u]) + __ldg(&w_bhh0[2048 + u]));
            float ov = sigf(s.w + __ldg(&w_bih0[3072 + u]) + __ldg(&w_bhh0[3072 + u]));
            float c = fv * __ldcg(&g_wc0[gid]) + iv * gv;
            g_wc0[gid] = c; g_wh0[gid] = ov * tanhf(c);
        }
        gridbar();
        // H: word LSTM1 gates (K = wh0 1024 + wh1 1024), split-16
        gstage(tid, cta, sX, sW, 8, 4096, 16, 128,
               g_wh0, 1024, w_Wih1, 1024, 0,
               g_wh1, 1024, w_Whh1, 1024, 0,
               1024, 0, nullptr, g_pbuf, 4096, nullptr, nullptr, 0, 0);
        gridbar();
        // I: word LSTM1 cell
        for (int gid = gt; gid < 32768; gid += G * 256) {
            int m = gid >> 10, u = gid & 1023;
            float4 s = make_float4(0.f, 0.f, 0.f, 0.f);
#pragma unroll
            for (int ks = 0; ks < 16; ks++) {
                float4 p = __ldcg((const float4*)&g_pbuf[(size_t)(ks * 32 + m) * 4096 + u * 4]);
                s.x += p.x; s.y += p.y; s.z += p.z; s.w += p.w;
            }
            float iv = sigf(s.x + __ldg(&w_bih1[u]) + __ldg(&w_bhh1[u]));
            float fv = sigf(s.y + __ldg(&w_bih1[1024 + u]) + __ldg(&w_bhh1[1024 + u]));
            float gv = tanhf(s.z + __ldg(&w_bih1[2048 + u]) + __ldg(&w_bhh1[2048 + u]));
            float ov = sigf(s.w + __ldg(&w_bih1[3072 + u]) + __ldg(&w_bhh1[3072 + u]));
            float c = fv * __ldcg(&g_wc1[gid]) + iv * gv;
            g_wc1[gid] = c; g_wh1[gid] = ov * tanhf(c);
        }
        gridbar();
    }
}

// precompute: out[2048][N] = table[idx[m]] @ Wrow^T (gate-interleaved rows), fp32 f32x2
struct Acc88 { ull a[8][4]; };
__device__ __forceinline__ void mm_inner(float (*As)[68], float (*Bs)[132],
                                         int rg, int cg, Acc88& A)
{
#pragma unroll
    for (int k = 0; k < 16; k++) {
        const float* xr = &As[k][rg * 8];
        float4 a0 = *(const float4*)xr, a1 = *(const float4*)(xr + 4);
        const float* br = &Bs[k][cg * 8];
        float4 b0 = *(const float4*)br, b1 = *(const float4*)(br + 4);
        ull bp0 = pk2(b0.x, b0.y), bp1 = pk2(b0.z, b0.w);
        ull bp2 = pk2(b1.x, b1.y), bp3 = pk2(b1.z, b1.w);
        float av[8] = {a0.x, a0.y, a0.z, a0.w, a1.x, a1.y, a1.z, a1.w};
#pragma unroll
        for (int r = 0; r < 8; r++) {
            ull ad = pk2(av[r], av[r]);
            fma2(A.a[r][0], ad, bp0);
            fma2(A.a[r][1], ad, bp1);
            fma2(A.a[r][2], ad, bp2);
            fma2(A.a[r][3], ad, bp3);
        }
    }
}

__global__ void __launch_bounds__(128, 4) k_pre(
    const int* __restrict__ idx, const float* __restrict__ table, int K,
    const float* __restrict__ W, int ldW, int H, float* __restrict__ out, int N)
{
    __shared__ float As[16][68];
    __shared__ float Bs[16][132];
    __shared__ const float* rp[64];
    int tid = threadIdx.x;
    int mb = blockIdx.y * 64, nb = blockIdx.x * 128;
    if (tid < 64) rp[tid] = table + (size_t)idx[mb + tid] * K;
    __syncthreads();
    Acc88 A;
#pragma unroll
    for (int r = 0; r < 8; r++)
#pragma unroll
        for (int c = 0; c < 4; c++) A.a[r][c] = 0ull;
    int rg = tid >> 4, cg = tid & 15;
    for (int k0 = 0; k0 < K; k0 += 16) {
#pragma unroll
        for (int i = tid; i < 256; i += 128) {
            int m = i & 63, kq = i >> 6;
            float4 v = *(const float4*)(rp[m] + k0 + kq * 4);
            As[kq * 4 + 0][m] = v.x; As[kq * 4 + 1][m] = v.y;
            As[kq * 4 + 2][m] = v.z; As[kq * 4 + 3][m] = v.w;
        }
#pragma unroll
        for (int i = tid; i < 512; i += 128) {
            int c = i & 127, kq = i >> 7;
            int gc = nb + c;
            float4 v = __ldg((const float4*)(W + (size_t)((gc & 3) * H + (gc >> 2)) * ldW + k0 + kq * 4));
            Bs[kq * 4 + 0][c] = v.x; Bs[kq * 4 + 1][c] = v.y;
            Bs[kq * 4 + 2][c] = v.z; Bs[kq * 4 + 3][c] = v.w;
        }
        __syncthreads();
        mm_inner(As, Bs, rg, cg, A);
        __syncthreads();
    }
#pragma unroll
    for (int r = 0; r < 8; r++) {
        float2 p0 = upk(A.a[r][0]), p1 = upk(A.a[r][1]);
        float2 p2 = upk(A.a[r][2]), p3 = upk(A.a[r][3]);
        float* op = out + (size_t)(mb + rg * 8 + r) * N + nb + cg * 8;
        *(float4*)op = make_float4(p0.x, p0.y, p1.x, p1.y);
        *(float4*)(op + 4) = make_float4(p2.x, p2.y, p3.x, p3.y);
    }
}

// ---- big logits GEMM via tf32 mma.sync: wout[2048,32000] = E @ W^T + b ----
// CTA 256 thr = 8 warps (2m x 4n), tile 64m x 128n, K-chunk 32, double-buffered.
__global__ void __launch_bounds__(256, 2) k_mma(
    const float* __restrict__ W, const float* __restrict__ bias, float* __restrict__ out)
{
    __shared__ unsigned sA[2][2048];   // [(mt*4+kk)*32+lane]*4+reg
    __shared__ unsigned sB[2][4096];   // [(nt*4+kk)*32+lane]*2+reg
    const int tid = threadIdx.x, lane = tid & 31, wid = tid >> 5;
    const int wm = wid & 1, wn = wid >> 1;
    const int mb = blockIdx.y * 64, nb = blockIdx.x * 128;

    float acc[2][4][4];
#pragma unroll
    for (int mt = 0; mt < 2; mt++)
#pragma unroll
        for (int j = 0; j < 4; j++)
#pragma unroll
            for (int r = 0; r < 4; r++) acc[mt][j][r] = 0.f;

    float4 ev[2], wv[4];

#define LDE(c)                                                                   \
    {                                                                            \
        _Pragma("unroll")                                                        \
        for (int j = 0; j < 2; j++) {                                            \
            int idx = tid * 2 + j, m = idx >> 3, kq = idx & 7;                   \
            ev[j] = *(const float4*)(g_ebuf + (size_t)(mb + m) * 512 + (c) * 32 + kq * 4); \
        }                                                                        \
        _Pragma("unroll")                                                        \
        for (int j = 0; j < 4; j++) {                                            \
            int idx = tid * 4 + j, n = idx >> 3, kq = idx & 7;                   \
            wv[j] = __ldg((const float4*)(W + (size_t)(nb + n) * 512 + (c) * 32 + kq * 4)); \
        }                                                                        \
    }
#define STE(buf)                                                                 \
    {                                                                            \
        _Pragma("unroll")                                                        \
        for (int j = 0; j < 2; j++) {                                            \
            int idx = tid * 2 + j, m = idx >> 3, kq = idx & 7, k0 = kq * 4;      \
            int mt = m >> 4, r = m & 15, kk = k0 >> 3;                           \
            int reg = (r >> 3) | (((k0 >> 2) & 1) << 1);                         \
            unsigned* p = &sA[buf][((mt * 4 + kk) * 32 + (r & 7) * 4) * 4 + reg];\
            float f[4] = {ev[j].x, ev[j].y, ev[j].z, ev[j].w};                   \
            _Pragma("unroll")                                                    \
            for (int i = 0; i < 4; i++) p[i * 4] = cvt_tf32(f[i]);               \
        }                                                                        \
        _Pragma("unroll")                                                        \
        for (int j = 0; j < 4; j++) {                                            \
            int idx = tid * 4 + j, n = idx >> 3, kq = idx & 7, k0 = kq * 4;      \
            int nt = n >> 3, col = n & 7, kk = k0 >> 3, reg = (k0 >> 2) & 1;     \
            unsigned* p = &sB[buf][((nt * 4 + kk) * 32 + col * 4) * 2 + reg];    \
            float f[4] = {wv[j].x, wv[j].y, wv[j].z, wv[j].w};                   \
            _Pragma("unroll")                                                    \
            for (int i = 0; i < 4; i++) p[i * 2] = cvt_tf32(f[i]);               \
        }                                                                        \
    }

    LDE(0); STE(0);
    __syncthreads();
#pragma unroll 1
    for (int c = 0; c < 16; c++) {
        int buf = c & 1;
        if (c < 15) LDE(c + 1);
#pragma unroll
        for (int kk = 0; kk < 4; kk++) {
            uint4 af[2];
#pragma unroll
            for (int mt = 0; mt < 2; mt++)
                af[mt] = *(const uint4*)&sA[buf][(((wm * 2 + mt) * 4 + kk) * 32 + lane) * 4];
#pragma unroll
            for (int j = 0; j < 4; j++) {
                uint2 bf = *(const uint2*)&sB[buf][(((wn * 4 + j) * 4 + kk) * 32 + lane) * 2];
                mma_tf32(acc[0][j], af[0], bf);
                mma_tf32(acc[1][j], af[1], bf);
            }
        }
        if (c < 15) { __syncthreads(); STE(buf ^ 1); __syncthreads(); }
    }

#pragma unroll
    for (int mt = 0; mt < 2; mt++) {
        int row0 = mb + (wm * 2 + mt) * 16 + (lane >> 2);
#pragma unroll
        for (int j = 0; j < 4; j++) {
            int col0 = nb + (wn * 4 + j) * 8 + (lane & 3) * 2;
            float2 bv = *(const float2*)&bias[col0];
            *(float2*)&out[(size_t)row0 * WORD_V + col0] =
                make_float2(acc[mt][j][0] + bv.x, acc[mt][j][1] + bv.y);
            *(float2*)&out[(size_t)(row0 + 8) * WORD_V + col0] =
                make_float2(acc[mt][j][2] + bv.x, acc[mt][j][3] + bv.y);
        }
    }
#undef LDE
#undef STE
}

__global__ void k_wnorm(float* __restrict__ wout)
{
    float* p = wout + (size_t)blockIdx.x * WORD_V;
    __shared__ float red[256];
    int tid = threadIdx.x;
    float m = -1e30f;
    for (int k = tid; k < WORD_V; k += 256) m = fmaxf(m, p[k]);
    red[tid] = m; __syncthreads();
    for (int s = 128; s > 0; s >>= 1) { if (tid < s) red[tid] = fmaxf(red[tid], red[tid + s]); __syncthreads(); }
    m = red[0]; __syncthreads();
    float s = 0.f;
    for (int k = tid; k < WORD_V; k += 256) s += expf(p[k] - m);
    red[tid] = s; __syncthreads();
    for (int st = 128; st > 0; st >>= 1) { if (tid < st) red[tid] += red[tid + st]; __syncthreads(); }
    float lse = m + logf(red[0]);
    for (int k = tid; k < WORD_V; k += 256) p[k] -= lse;
}

extern "C" void kernel_launch(void* const* d_in, const int* in_sizes, int n_in,
                              void* d_out, int out_size)
{
    const int*   pos          = (const int*)  d_in[0];
    const int*   word         = (const int*)  d_in[1];
    const float* pos_emb_W    = (const float*)d_in[2];
    const float* word_emb_W   = (const float*)d_in[3];
    const float* w2p_W        = (const float*)d_in[4];
    const float* w2p_b        = (const float*)d_in[5];
    const float* p2w_W        = (const float*)d_in[6];
    const float* p2w_b        = (const float*)d_in[7];
    const float* p_Wih0       = (const float*)d_in[8];
    const float* p_Whh0       = (const float*)d_in[9];
    const float* p_bih0       = (const float*)d_in[10];
    const float* p_bhh0       = (const float*)d_in[11];
    const float* w_Wih0       = (const float*)d_in[12];
    const float* w_Whh0       = (const float*)d_in[13];
    const float* w_bih0       = (const float*)d_in[14];
    const float* w_bhh0       = (const float*)d_in[15];
    const float* w_Wih1       = (const float*)d_in[16];
    const float* w_Whh1       = (const float*)d_in[17];
    const float* w_bih1       = (const float*)d_in[18];
    const float* w_bhh1       = (const float*)d_in[19];
    const float* pos_proj_W   = (const float*)d_in[20];
    const float* pos_proj_b   = (const float*)d_in[21];
    const float* word_proj1_W = (const float*)d_in[22];
    const float* word_proj1_b = (const float*)d_in[23];
    const float* word_proj2_b = (const float*)d_in[24];

    float* pih = nullptr;  cudaGetSymbolAddress((void**)&pih,  g_PIH);
    float* wih = nullptr;  cudaGetSymbolAddress((void**)&wih,  g_WIH0);

    float* pout = (float*)d_out;
    float* wout = pout + (size_t)TT * 32 * 48;

    // hoisted input projections (token-indexed, independent of recurrence)
    k_pre<<<dim3(8, 32), 128>>>(pos, pos_emb_W, 128, p_Wih0, 1152, 256, pih, 1024);
    k_pre<<<dim3(32, 32), 128>>>(word, word_emb_W, 512, w_Wih0, 768, 1024, wih, 4096);

    // the whole 64-step recurrence in ONE persistent kernel
    k_loop<<<G, 256>>>(w2p_W, w2p_b, p2w_W, p2w_b,
                       p_Wih0, p_Whh0, p_bih0, p_bhh0,
                       w_Wih0, w_Whh0, w_bih0, w_bhh0,
                       w_Wih1, w_Whh1, w_bih1, w_bhh1,
                       pos_proj_W, pos_proj_b, word_proj1_W, word_proj1_b, pout);

    // hoisted logits GEMM (tf32 tensor cores) + final log-softmax
    k_mma<<<dim3(WORD_V / 128, 32), 256>>>(word_emb_W, word_proj2_b, wout);
    k_wnorm<<<TT * 32, 256>>>(wout);
}

// round 9
// speedup vs baseline: 2.8335x; 1.2042x over previous
#include <cuda_runtime.h>
#include <math.h>

#define TT 64
#define WORD_V 32000
#define G 148

typedef unsigned long long ull;

__device__ __align__(16) float g_ph[32 * 256];
__device__ __align__(16) float g_pc[32 * 256];
__device__ __align__(16) float g_wh0[32 * 1024];
__device__ __align__(16) float g_wc0[32 * 1024];
__device__ __align__(16) float g_wh1[32 * 1024];
__device__ __align__(16) float g_wc1[32 * 1024];
__device__ __align__(16) float g_ebuf[2048 * 512];
__device__ __align__(16) float g_PIH[2048 * 1024];
__device__ __align__(16) float g_WIH0[2048 * 4096];
__device__ __align__(16) float g_pbuf[4194304];
__device__ __align__(16) float g_pbufE[65536];
__device__ unsigned g_cnt;
__device__ volatile unsigned g_gen;

#define PBUF_C 1310720   // stage-C partial region offset inside g_pbuf

__device__ __forceinline__ void gridbar() {
    __threadfence();
    __syncthreads();
    if (threadIdx.x == 0) {
        unsigned gen = g_gen;
        if (atomicAdd(&g_cnt, 1u) == G - 1) { g_cnt = 0; __threadfence(); g_gen = gen + 1; }
        else { while (g_gen == gen) { } }
    }
    __syncthreads();
}

__device__ __forceinline__ float sigf(float x) { return 1.f / (1.f + expf(-x)); }

__device__ __forceinline__ ull pk2(float lo, float hi) {
    ull r; asm("mov.b64 %0, {%1, %2};" : "=l"(r) : "f"(lo), "f"(hi)); return r;
}
__device__ __forceinline__ void fma2(ull& d, ull a, ull b) {
    asm("fma.rn.f32x2 %0, %1, %2, %3;" : "=l"(d) : "l"(a), "l"(b), "l"(d));
}
__device__ __forceinline__ float2 upk(ull v) {
    float2 f; asm("mov.b64 {%0, %1}, %2;" : "=f"(f.x), "=f"(f.y) : "l"(v)); return f;
}
__device__ __forceinline__ unsigned cvt_tf32(float f) {
    unsigned u; asm("cvt.rna.tf32.f32 %0, %1;" : "=r"(u) : "f"(f)); return u;
}
__device__ __forceinline__ void mma_tf32(float* d, uint4 a, uint2 b) {
    asm("mma.sync.aligned.m16n8k8.row.col.f32.tf32.tf32.f32 "
        "{%0,%1,%2,%3}, {%4,%5,%6,%7}, {%8,%9}, {%0,%1,%2,%3};"
        : "+f"(d[0]), "+f"(d[1]), "+f"(d[2]), "+f"(d[3])
        : "r"(a.x), "r"(a.y), "r"(a.z), "r"(a.w), "r"(b.x), "r"(b.y));
}

// ---- stage GEMM: tasks = (32 x TW col-tile) x split-K; writes partials ----
// If xaPart != null, seg0 X[m][c] = tanh(sum_{s<xaNs} xaPart[(s*32+m)*xaStride + c] + xaBias[c]).
template<int TW>
__device__ __noinline__ void gstage(
    int tid, int cta, float* sX, float* sW,
    int ncolt, int ncols, int ksplit, int kc,
    const float* Xa, int Ka, const float* Wa, int lda, int cba,
    const float* Xb, int Kb, const float* Wb, int ldb, int cbb,
    int H, int ws, const float* Wc,
    float* out, int ostride,
    const float* xaPart, const float* xaBias, int xaNs, int xaStride)
{
    constexpr int CG   = TW / 8;      // col-groups
    constexpr int RPG  = TW / 64;     // rows per thread (512->8, 256->4)
    constexpr int WSTR = TW + 8;
    constexpr int WF4  = TW / 64;     // W float4 loads per thread per chunk
    const int rg = tid / CG, cg = tid % CG;
    const int xm = tid & 31, xq = (tid >> 5) & 3;
    const int ntasks = ncolt * ksplit;

    for (int task = cta; task < ntasks; task += G) {
        const int ct = task % ncolt, ks = task / ncolt;
        const int kbeg = ks * kc, kend = kbeg + kc;
        ull acc[RPG][4];
#pragma unroll
        for (int r = 0; r < RPG; r++)
#pragma unroll
            for (int c = 0; c < 4; c++) acc[r][c] = 0ull;
        int base = 0;
#pragma unroll 1
        for (int seg = 0; seg < 2; seg++) {
            const float* Xp = seg ? Xb : Xa;
            const float* Wp = seg ? Wb : Wa;
            const int K = seg ? Kb : Ka, ld = seg ? ldb : lda, cb = seg ? cbb : cba;
            if (K > 0) {
                int lo = kbeg > base ? kbeg : base;
                int hi = kend < base + K ? kend : base + K;
                if (lo < hi) {
                    const bool fuse = (seg == 0) && (xaPart != nullptr);
                    const float* xrow = fuse ? nullptr : (Xp + (size_t)xm * K);
                    // precompute W row pointers (constant per task/seg)
                    const float* wp[WF4];
#pragma unroll
                    for (int j = 0; j < WF4; j++) {
                        int i = tid + j * 256;
                        int c = i % TW, kq = i / TW;
                        int gc = ct * TW + c;
                        if (gc >= ncols) gc = ncols - 1;
                        const float* wr;
                        if (H > 0)        wr = Wp + (size_t)((gc & 3) * H + (gc >> 2)) * ld + cb;
                        else if (gc < ws) wr = Wp + (size_t)gc * ld + cb;
                        else              wr = Wc + (size_t)(gc - ws) * ld + cb;
                        wp[j] = wr + kq * 4;
                    }
                    float4 rx = make_float4(0.f, 0.f, 0.f, 0.f);
                    float4 rw[WF4];

#define LOADX(xo)                                                                 \
    if (tid < 128) {                                                              \
        if (fuse) {                                                               \
            int col0 = (xo) + xq * 4;                                             \
            float4 s = *(const float4*)&xaBias[col0];                             \
            for (int sp = 0; sp < xaNs; sp++) {                                   \
                float4 p = __ldcg((const float4*)&xaPart[(size_t)(sp * 32 + xm) * xaStride + col0]); \
                s.x += p.x; s.y += p.y; s.z += p.z; s.w += p.w;                    \
            }                                                                     \
            rx = make_float4(tanhf(s.x), tanhf(s.y), tanhf(s.z), tanhf(s.w));     \
        } else {                                                                  \
            rx = __ldcg((const float4*)(xrow + (xo) + xq * 4));                   \
        }                                                                         \
    }
#define LOADW(xo)                                                                 \
    _Pragma("unroll")                                                             \
    for (int j = 0; j < WF4; j++) rw[j] = __ldg((const float4*)(wp[j] + (xo)));

                    LOADX(lo - base);
                    LOADW(lo - base);
#pragma unroll 1
                    for (int k0 = lo; k0 < hi; k0 += 16) {
                        if (tid < 128) {
                            sX[(xq * 4 + 0) * 36 + xm] = rx.x;
                            sX[(xq * 4 + 1) * 36 + xm] = rx.y;
                            sX[(xq * 4 + 2) * 36 + xm] = rx.z;
                            sX[(xq * 4 + 3) * 36 + xm] = rx.w;
                        }
#pragma unroll
                        for (int j = 0; j < WF4; j++) {
                            int i = tid + j * 256;
                            int c = i % TW, kq4 = (i / TW) * 4;
                            sW[(kq4 + 0) * WSTR + c] = rw[j].x;
                            sW[(kq4 + 1) * WSTR + c] = rw[j].y;
                            sW[(kq4 + 2) * WSTR + c] = rw[j].z;
                            sW[(kq4 + 3) * WSTR + c] = rw[j].w;
                        }
                        __syncthreads();
                        if (k0 + 16 < hi) {     // prefetch next chunk
                            LOADX(k0 + 16 - base);
                            LOADW(k0 + 16 - base);
                        }
#pragma unroll
                        for (int k = 0; k < 16; k++) {
                            float av[RPG];
                            const float* xr = &sX[k * 36 + rg * RPG];
#pragma unroll
                            for (int rr = 0; rr < RPG / 4; rr++) {
                                float4 a = *(const float4*)(xr + rr * 4);
                                av[rr * 4 + 0] = a.x; av[rr * 4 + 1] = a.y;
                                av[rr * 4 + 2] = a.z; av[rr * 4 + 3] = a.w;
                            }
                            const float* br = &sW[k * WSTR + cg * 8];
                            float4 b0 = *(const float4*)br, b1 = *(const float4*)(br + 4);
                            ull bp0 = pk2(b0.x, b0.y), bp1 = pk2(b0.z, b0.w);
                            ull bp2 = pk2(b1.x, b1.y), bp3 = pk2(b1.z, b1.w);
#pragma unroll
                            for (int r = 0; r < RPG; r++) {
                                ull ad = pk2(av[r], av[r]);
                                fma2(acc[r][0], ad, bp0);
                                fma2(acc[r][1], ad, bp1);
                                fma2(acc[r][2], ad, bp2);
                                fma2(acc[r][3], ad, bp3);
                            }
                        }
                        __syncthreads();
                    }
#undef LOADX
#undef LOADW
                }
            }
            base += K;
        }
        int oc = ct * TW + cg * 8;
        if (oc < ncols) {
#pragma unroll
            for (int r = 0; r < RPG; r++) {
                float2 p0 = upk(acc[r][0]), p1 = upk(acc[r][1]);
                float2 p2 = upk(acc[r][2]), p3 = upk(acc[r][3]);
                float* op = &out[(size_t)(ks * 32 + rg * RPG + r) * ostride + oc];
                *(float4*)op = make_float4(p0.x, p0.y, p1.x, p1.y);
                *(float4*)(op + 4) = make_float4(p2.x, p2.y, p3.x, p3.y);
            }
        }
    }
}

__global__ void __launch_bounds__(256, 1) k_loop(
    const float* __restrict__ w2p_W, const float* __restrict__ w2p_b,
    const float* __restrict__ p2w_W, const float* __restrict__ p2w_b,
    const float* __restrict__ p_Wih0, const float* __restrict__ p_Whh0,
    const float* __restrict__ p_bih0, const float* __restrict__ p_bhh0,
    const float* __restrict__ w_Wih0, const float* __restrict__ w_Whh0,
    const float* __restrict__ w_bih0, const float* __restrict__ w_bhh0,
    const float* __restrict__ w_Wih1, const float* __restrict__ w_Whh1,
    const float* __restrict__ w_bih1, const float* __restrict__ w_bhh1,
    const float* __restrict__ pos_proj_W, const float* __restrict__ pos_proj_b,
    const float* __restrict__ word_proj1_W, const float* __restrict__ word_proj1_b,
    float* __restrict__ pout)
{
    __shared__ float sX[16 * 36];
    __shared__ float sW[16 * 520];
    const int tid = threadIdx.x, cta = blockIdx.x;
    const int gt = cta * 256 + tid;

    { // zero states
        float4 z = make_float4(0.f, 0.f, 0.f, 0.f);
        if (gt < 2048) { ((float4*)g_ph)[gt] = z; ((float4*)g_pc)[gt] = z; }
        if (gt < 8192) { ((float4*)g_wh0)[gt] = z; ((float4*)g_wc0)[gt] = z;
                         ((float4*)g_wh1)[gt] = z; ((float4*)g_wc1)[gt] = z; }
    }
    gridbar();

    for (int t = 0; t <= TT; t++) {
        // A: pbuf = wh1 @ [w2p_W | word_proj1_W]^T  (1536 cols, K=1024, split-22, kc=48)
        gstage<256>(tid, cta, sX, sW, 6, 1536, 22, 48,
                    g_wh1, 1024, w2p_W, 1024, 0,
                    nullptr, 0, nullptr, 0, 0,
                    0, 1024, word_proj1_W, g_pbuf, 1536, nullptr, nullptr, 0, 0);
        gridbar();
        if (t == TT) {   // final ebuf reduce (for t-1), then done
            for (int idx = gt; idx < 4096; idx += G * 256) {
                int m = idx >> 7, cq = idx & 127;
                float4 s = *(const float4*)&word_proj1_b[cq * 4];
#pragma unroll
                for (int ks = 0; ks < 22; ks++) {
                    float4 p = __ldcg((const float4*)&g_pbuf[(size_t)(ks * 32 + m) * 1536 + 1024 + cq * 4]);
                    s.x += p.x; s.y += p.y; s.z += p.z; s.w += p.w;
                }
                *(float4*)&g_ebuf[(size_t)((t - 1) * 32 + m) * 512 + cq * 4] = s;
            }
            break;
        }
        // C: pos gates (K = lastw 1024 fused-from-partials + ph 256), ncolt4/split27/kc48;
        //    spare CTAs (108..147) reduce ebuf_{t-1} from pbuf cols 1024-1535.
        gstage<256>(tid, cta, sX, sW, 4, 1024, 27, 48,
                    nullptr, 1024, p_Wih0, 1152, 128,
                    g_ph, 256, p_Whh0, 256, 0,
                    256, 0, nullptr, g_pbuf + PBUF_C, 1024, g_pbuf, w2p_b, 22, 1536);
        if (cta >= 108 && t >= 1) {
            for (int idx = (cta - 108) * 256 + tid; idx < 4096; idx += 40 * 256) {
                int m = idx >> 7, cq = idx & 127;
                float4 s = *(const float4*)&word_proj1_b[cq * 4];
#pragma unroll
                for (int ks = 0; ks < 22; ks++) {
                    float4 p = __ldcg((const float4*)&g_pbuf[(size_t)(ks * 32 + m) * 1536 + 1024 + cq * 4]);
                    s.x += p.x; s.y += p.y; s.z += p.z; s.w += p.w;
                }
                *(float4*)&g_ebuf[(size_t)((t - 1) * 32 + m) * 512 + cq * 4] = s;
            }
        }
        gridbar();
        // D: pos cell update (27 splits at PBUF_C)
        for (int gid = gt; gid < 8192; gid += G * 256) {
            int m = gid >> 8, u = gid & 255;
            float4 s = __ldg((const float4*)&g_PIH[(size_t)(t * 32 + m) * 1024 + u * 4]);
#pragma unroll
            for (int ks = 0; ks < 27; ks++) {
                float4 p = __ldcg((const float4*)&g_pbuf[PBUF_C + (size_t)(ks * 32 + m) * 1024 + u * 4]);
                s.x += p.x; s.y += p.y; s.z += p.z; s.w += p.w;
            }
            float iv = sigf(s.x + __ldg(&p_bih0[u]) + __ldg(&p_bhh0[u]));
            float fv = sigf(s.y + __ldg(&p_bih0[256 + u]) + __ldg(&p_bhh0[256 + u]));
            float gv = tanhf(s.z + __ldg(&p_bih0[512 + u]) + __ldg(&p_bhh0[512 + u]));
            float ov = sigf(s.w + __ldg(&p_bih0[768 + u]) + __ldg(&p_bhh0[768 + u]));
            float c = fv * __ldcg(&g_pc[gid]) + iv * gv;
            g_pc[gid] = c; g_ph[gid] = ov * tanhf(c);
        }
        gridbar();
        // E: lastp partials (CTAs 0-7, split-8/kc32) + pos logits (CTAs 8-39)
        gstage<256>(tid, cta, sX, sW, 1, 256, 8, 32,
                    g_ph, 256, p2w_W, 256, 0,
                    nullptr, 0, nullptr, 0, 0,
                    0, 1 << 30, nullptr, g_pbufE, 256, nullptr, nullptr, 0, 0);
        if (cta >= 8 && cta < 40) {
            int r = cta - 8;
            float v = 0.f;
            if (tid < 48) {
                v = __ldg(&pos_proj_b[tid]);
                const float4* xp = (const float4*)(g_ph + r * 256);
                const float4* wp = (const float4*)(pos_proj_W + tid * 256);
#pragma unroll 8
                for (int k = 0; k < 64; k++) {
                    float4 x = __ldcg(xp + k), w = __ldg(wp + k);
                    v = fmaf(x.x, w.x, v); v = fmaf(x.y, w.y, v);
                    v = fmaf(x.z, w.z, v); v = fmaf(x.w, w.w, v);
                }
                sW[tid] = v;
            }
            __syncthreads();
            if (tid == 0) {
                float mx = -1e30f;
                for (int k = 0; k < 48; k++) mx = fmaxf(mx, sW[k]);
                float sm = 0.f;
                for (int k = 0; k < 48; k++) sm += expf(sW[k] - mx);
                sW[48] = mx + logf(sm);
            }
            __syncthreads();
            if (tid < 48) pout[((size_t)t * 32 + r) * 48 + tid] = v - sW[48];
        }
        gridbar();
        // F: word LSTM0 gates (K = lastp 256 fused + wh0 1024), 8x16, kc 80
        gstage<512>(tid, cta, sX, sW, 8, 4096, 16, 80,
                    nullptr, 256, w_Wih0, 768, 512,
                    g_wh0, 1024, w_Whh0, 1024, 0,
                    1024, 0, nullptr, g_pbuf, 4096, g_pbufE, p2w_b, 8, 256);
        gridbar();
        // G: word LSTM0 cell
        for (int gid = gt; gid < 32768; gid += G * 256) {
            int m = gid >> 10, u = gid & 1023;
            float4 s = __ldg((const float4*)&g_WIH0[(size_t)(t * 32 + m) * 4096 + u * 4]);
#pragma unroll
            for (int ks = 0; ks < 16; ks++) {
                float4 p = __ldcg((const float4*)&g_pbuf[(size_t)(ks * 32 + m) * 4096 + u * 4]);
                s.x += p.x; s.y += p.y; s.z += p.z; s.w += p.w;
            }
            float iv = sigf(s.x + __ldg(&w_bih0[u]) + __ldg(&w_bhh0[u]));
            float fv = sigf(s.y + __ldg(&w_bih0[1024 + u]) + __ldg(&w_bhh0[1024 + u]));
            float gv = tanhf(s.z + __ldg(&w_bih0[2048 + u]) + __ldg(&w_bhh0[2048 + u]));
            float ov = sigf(s.w + __ldg(&w_bih0[3072 + u]) + __ldg(&w_bhh0[3072 + u]));
            float c = fv * __ldcg(&g_wc0[gid]) + iv * gv;
            g_wc0[gid] = c; g_wh0[gid] = ov * tanhf(c);
        }
        gridbar();
        // H: word LSTM1 gates (K = wh0 1024 + wh1 1024), 8x16, kc 128
        gstage<512>(tid, cta, sX, sW, 8, 4096, 16, 128,
                    g_wh0, 1024, w_Wih1, 1024, 0,
                    g_wh1, 1024, w_Whh1, 1024, 0,
                    1024, 0, nullptr, g_pbuf, 4096, nullptr, nullptr, 0, 0);
        gridbar();
        // I: word LSTM1 cell
        for (int gid = gt; gid < 32768; gid += G * 256) {
            int m = gid >> 10, u = gid & 1023;
            float4 s = make_float4(0.f, 0.f, 0.f, 0.f);
#pragma unroll
            for (int ks = 0; ks < 16; ks++) {
                float4 p = __ldcg((const float4*)&g_pbuf[(size_t)(ks * 32 + m) * 4096 + u * 4]);
                s.x += p.x; s.y += p.y; s.z += p.z; s.w += p.w;
            }
            float iv = sigf(s.x + __ldg(&w_bih1[u]) + __ldg(&w_bhh1[u]));
            float fv = sigf(s.y + __ldg(&w_bih1[1024 + u]) + __ldg(&w_bhh1[1024 + u]));
            float gv = tanhf(s.z + __ldg(&w_bih1[2048 + u]) + __ldg(&w_bhh1[2048 + u]));
            float ov = sigf(s.w + __ldg(&w_bih1[3072 + u]) + __ldg(&w_bhh1[3072 + u]));
            float c = fv * __ldcg(&g_wc1[gid]) + iv * gv;
            g_wc1[gid] = c; g_wh1[gid] = ov * tanhf(c);
        }
        gridbar();
    }
}

// precompute: out[2048][N] = table[idx[m]] @ Wrow^T (gate-interleaved rows), fp32 f32x2
struct Acc88 { ull a[8][4]; };
__device__ __forceinline__ void mm_inner(float (*As)[68], float (*Bs)[132],
                                         int rg, int cg, Acc88& A)
{
#pragma unroll
    for (int k = 0; k < 16; k++) {
        const float* xr = &As[k][rg * 8];
        float4 a0 = *(const float4*)xr, a1 = *(const float4*)(xr + 4);
        const float* br = &Bs[k][cg * 8];
        float4 b0 = *(const float4*)br, b1 = *(const float4*)(br + 4);
        ull bp0 = pk2(b0.x, b0.y), bp1 = pk2(b0.z, b0.w);
        ull bp2 = pk2(b1.x, b1.y), bp3 = pk2(b1.z, b1.w);
        float av[8] = {a0.x, a0.y, a0.z, a0.w, a1.x, a1.y, a1.z, a1.w};
#pragma unroll
        for (int r = 0; r < 8; r++) {
            ull ad = pk2(av[r], av[r]);
            fma2(A.a[r][0], ad, bp0);
            fma2(A.a[r][1], ad, bp1);
            fma2(A.a[r][2], ad, bp2);
            fma2(A.a[r][3], ad, bp3);
        }
    }
}

__global__ void __launch_bounds__(128, 4) k_pre(
    const int* __restrict__ idx, const float* __restrict__ table, int K,
    const float* __restrict__ W, int ldW, int H, float* __restrict__ out, int N)
{
    __shared__ float As[16][68];
    __shared__ float Bs[16][132];
    __shared__ const float* rp[64];
    int tid = threadIdx.x;
    int mb = blockIdx.y * 64, nb = blockIdx.x * 128;
    if (tid < 64) rp[tid] = table + (size_t)idx[mb + tid] * K;
    __syncthreads();
    Acc88 A;
#pragma unroll
    for (int r = 0; r < 8; r++)
#pragma unroll
        for (int c = 0; c < 4; c++) A.a[r][c] = 0ull;
    int rg = tid >> 4, cg = tid & 15;
    for (int k0 = 0; k0 < K; k0 += 16) {
#pragma unroll
        for (int i = tid; i < 256; i += 128) {
            int m = i & 63, kq = i >> 6;
            float4 v = *(const float4*)(rp[m] + k0 + kq * 4);
            As[kq * 4 + 0][m] = v.x; As[kq * 4 + 1][m] = v.y;
            As[kq * 4 + 2][m] = v.z; As[kq * 4 + 3][m] = v.w;
        }
#pragma unroll
        for (int i = tid; i < 512; i += 128) {
            int c = i & 127, kq = i >> 7;
            int gc = nb + c;
            float4 v = __ldg((const float4*)(W + (size_t)((gc & 3) * H + (gc >> 2)) * ldW + k0 + kq * 4));
            Bs[kq * 4 + 0][c] = v.x; Bs[kq * 4 + 1][c] = v.y;
            Bs[kq * 4 + 2][c] = v.z; Bs[kq * 4 + 3][c] = v.w;
        }
        __syncthreads();
        mm_inner(As, Bs, rg, cg, A);
        __syncthreads();
    }
#pragma unroll
    for (int r = 0; r < 8; r++) {
        float2 p0 = upk(A.a[r][0]), p1 = upk(A.a[r][1]);
        float2 p2 = upk(A.a[r][2]), p3 = upk(A.a[r][3]);
        float* op = out + (size_t)(mb + rg * 8 + r) * N + nb + cg * 8;
        *(float4*)op = make_float4(p0.x, p0.y, p1.x, p1.y);
        *(float4*)(op + 4) = make_float4(p2.x, p2.y, p3.x, p3.y);
    }
}

// ---- big logits GEMM via tf32 mma.sync: wout[2048,32000] = E @ W^T + b ----
// 256 thr = 8 warps (2m x 4n), tile 64m x 128n, K-chunk 32, natural [row][k] smem
// (stride 36: conflict-free STS.128 stores AND 4r+k fragment gathers), reg prefetch.
__global__ void __launch_bounds__(256, 2) k_mma(
    const float* __restrict__ W, const float* __restrict__ bias, float* __restrict__ out)
{
    __shared__ unsigned sA[64 * 36];
    __shared__ unsigned sB[128 * 36];
    const int tid = threadIdx.x, lane = tid & 31, wid = tid >> 5;
    const int wm = wid & 1, wn = wid >> 1;
    const int mb = blockIdx.y * 64, nb = blockIdx.x * 128;

    float acc[2][4][4];
#pragma unroll
    for (int mt = 0; mt < 2; mt++)
#pragma unroll
        for (int j = 0; j < 4; j++)
#pragma unroll
            for (int r = 0; r < 4; r++) acc[mt][j][r] = 0.f;

    // global pointers + smem store addresses (constant across chunks)
    const float* eptr[2]; unsigned* sa[2];
    const float* wptr[4]; unsigned* sb[4];
#pragma unroll
    for (int j = 0; j < 2; j++) {
        int idx = tid * 2 + j, m = idx >> 3, kq = idx & 7;
        eptr[j] = g_ebuf + (size_t)(mb + m) * 512 + kq * 4;
        sa[j] = &sA[m * 36 + kq * 4];
    }
#pragma unroll
    for (int j = 0; j < 4; j++) {
        int idx = tid * 4 + j, n = idx >> 3, kq = idx & 7;
        wptr[j] = W + (size_t)(nb + n) * 512 + kq * 4;
        sb[j] = &sB[n * 36 + kq * 4];
    }
    const int arow = wm * 32 + (lane >> 2);       // + mt*16
    const int kcol0 = lane & 3;                    // + kk*8 (+4)
    const int nrow0 = wn * 32 + (lane >> 2);       // + j*8

    float4 ev[2], wv[4];
#define LDE(c)                                                        \
    { _Pragma("unroll") for (int j = 0; j < 2; j++) ev[j] = __ldcg((const float4*)(eptr[j] + (c) * 32)); \
      _Pragma("unroll") for (int j = 0; j < 4; j++) wv[j] = __ldg((const float4*)(wptr[j] + (c) * 32)); }
#define STE()                                                         \
    { _Pragma("unroll") for (int j = 0; j < 2; j++)                   \
          *(uint4*)sa[j] = make_uint4(cvt_tf32(ev[j].x), cvt_tf32(ev[j].y), cvt_tf32(ev[j].z), cvt_tf32(ev[j].w)); \
      _Pragma("unroll") for (int j = 0; j < 4; j++)                   \
          *(uint4*)sb[j] = make_uint4(cvt_tf32(wv[j].x), cvt_tf32(wv[j].y), cvt_tf32(wv[j].z), cvt_tf32(wv[j].w)); }

    LDE(0);
#pragma unroll 1
    for (int c = 0; c < 16; c++) {
        STE();
        __syncthreads();
        if (c < 15) LDE(c + 1);
#pragma unroll
        for (int kk = 0; kk < 4; kk++) {
            int kc0 = kk * 8 + kcol0;
            uint4 af[2];
#pragma unroll
            for (int mt = 0; mt < 2; mt++) {
                int r0 = arow + mt * 16;
                af[mt].x = sA[r0 * 36 + kc0];
                af[mt].y = sA[(r0 + 8) * 36 + kc0];
                af[mt].z = sA[r0 * 36 + kc0 + 4];
                af[mt].w = sA[(r0 + 8) * 36 + kc0 + 4];
            }
#pragma unroll
            for (int j = 0; j < 4; j++) {
                int nr = nrow0 + j * 8;
                uint2 bf;
                bf.x = sB[nr * 36 + kc0];
                bf.y = sB[nr * 36 + kc0 + 4];
                mma_tf32(acc[0][j], af[0], bf);
                mma_tf32(acc[1][j], af[1], bf);
            }
        }
        __syncthreads();
    }
#undef LDE
#undef STE

#pragma unroll
    for (int mt = 0; mt < 2; mt++) {
        int row0 = mb + wm * 32 + mt * 16 + (lane >> 2);
#pragma unroll
        for (int j = 0; j < 4; j++) {
            int col0 = nb + wn * 32 + j * 8 + (lane & 3) * 2;
            float2 bv = *(const float2*)&bias[col0];
            *(float2*)&out[(size_t)row0 * WORD_V + col0] =
                make_float2(acc[mt][j][0] + bv.x, acc[mt][j][1] + bv.y);
            *(float2*)&out[(size_t)(row0 + 8) * WORD_V + col0] =
                make_float2(acc[mt][j][2] + bv.x, acc[mt][j][3] + bv.y);
        }
    }
}

__global__ void k_wnorm(float* __restrict__ wout)
{
    float* p = wout + (size_t)blockIdx.x * WORD_V;
    __shared__ float red[256];
    int tid = threadIdx.x;
    float m = -1e30f;
    for (int k = tid; k < WORD_V; k += 256) m = fmaxf(m, p[k]);
    red[tid] = m; __syncthreads();
    for (int s = 128; s > 0; s >>= 1) { if (tid < s) red[tid] = fmaxf(red[tid], red[tid + s]); __syncthreads(); }
    m = red[0]; __syncthreads();
    float s = 0.f;
    for (int k = tid; k < WORD_V; k += 256) s += expf(p[k] - m);
    red[tid] = s; __syncthreads();
    for (int st = 128; st > 0; st >>= 1) { if (tid < st) red[tid] += red[tid + st]; __syncthreads(); }
    float lse = m + logf(red[0]);
    for (int k = tid; k < WORD_V; k += 256) p[k] -= lse;
}

extern "C" void kernel_launch(void* const* d_in, const int* in_sizes, int n_in,
                              void* d_out, int out_size)
{
    const int*   pos          = (const int*)  d_in[0];
    const int*   word         = (const int*)  d_in[1];
    const float* pos_emb_W    = (const float*)d_in[2];
    const float* word_emb_W   = (const float*)d_in[3];
    const float* w2p_W        = (const float*)d_in[4];
    const float* w2p_b        = (const float*)d_in[5];
    const float* p2w_W        = (const float*)d_in[6];
    const float* p2w_b        = (const float*)d_in[7];
    const float* p_Wih0       = (const float*)d_in[8];
    const float* p_Whh0       = (const float*)d_in[9];
    const float* p_bih0       = (const float*)d_in[10];
    const float* p_bhh0       = (const float*)d_in[11];
    const float* w_Wih0       = (const float*)d_in[12];
    const float* w_Whh0       = (const float*)d_in[13];
    const float* w_bih0       = (const float*)d_in[14];
    const float* w_bhh0       = (const float*)d_in[15];
    const float* w_Wih1       = (const float*)d_in[16];
    const float* w_Whh1       = (const float*)d_in[17];
    const float* w_bih1       = (const float*)d_in[18];
    const float* w_bhh1       = (const float*)d_in[19];
    const float* pos_proj_W   = (const float*)d_in[20];
    const float* pos_proj_b   = (const float*)d_in[21];
    const float* word_proj1_W = (const float*)d_in[22];
    const float* word_proj1_b = (const float*)d_in[23];
    const float* word_proj2_b = (const float*)d_in[24];

    float* pih = nullptr;  cudaGetSymbolAddress((void**)&pih,  g_PIH);
    float* wih = nullptr;  cudaGetSymbolAddress((void**)&wih,  g_WIH0);

    float* pout = (float*)d_out;
    float* wout = pout + (size_t)TT * 32 * 48;

    // hoisted input projections (token-indexed, independent of recurrence)
    k_pre<<<dim3(8, 32), 128>>>(pos, pos_emb_W, 128, p_Wih0, 1152, 256, pih, 1024);
    k_pre<<<dim3(32, 32), 128>>>(word, word_emb_W, 512, w_Wih0, 768, 1024, wih, 4096);

    // the whole 64-step recurrence in ONE persistent kernel
    k_loop<<<G, 256>>>(w2p_W, w2p_b, p2w_W, p2w_b,
                       p_Wih0, p_Whh0, p_bih0, p_bhh0,
                       w_Wih0, w_Whh0, w_bih0, w_bhh0,
                       w_Wih1, w_Whh1, w_bih1, w_bhh1,
                       pos_proj_W, pos_proj_b, word_proj1_W, word_proj1_b, pout);

    // hoisted logits GEMM (tf32 tensor cores) + final log-softmax
    k_mma<<<dim3(WORD_V / 128, 32), 256>>>(word_emb_W, word_proj2_b, wout);
    k_wnorm<<<TT * 32, 256>>>(wout);
}

// round 10
// speedup vs baseline: 3.3621x; 1.1866x over previous
#include <cuda_runtime.h>
#include <math.h>

#define TT 64
#define WORD_V 32000
#define G 148

typedef unsigned long long ull;

__device__ __align__(16) float g_ph[32 * 256];
__device__ __align__(16) float g_pc[32 * 256];
__device__ __align__(16) float g_wh0[32 * 1024];
__device__ __align__(16) float g_wc0[32 * 1024];
__device__ __align__(16) float g_wh1[32 * 1024];
__device__ __align__(16) float g_wc1[32 * 1024];
__device__ __align__(16) float g_whist[2048 * 1024];
__device__ __align__(16) float g_ebuf[2048 * 512];
__device__ __align__(16) float g_PIH[2048 * 1024];
__device__ __align__(16) float g_WIH0[2048 * 4096];
__device__ __align__(16) float g_pbuf[4194304];
__device__ __align__(16) float g_pbufE[65536];
__device__ unsigned g_cnt;
__device__ volatile unsigned g_gen;

#define PBUF_C 2097152

__device__ __forceinline__ void gridbar() {
    __threadfence();
    __syncthreads();
    if (threadIdx.x == 0) {
        unsigned gen = g_gen;
        if (atomicAdd(&g_cnt, 1u) == G - 1) { g_cnt = 0; __threadfence(); g_gen = gen + 1; }
        else { while (g_gen == gen) { } }
    }
    __syncthreads();
}

__device__ __forceinline__ float sigf(float x) { return 1.f / (1.f + expf(-x)); }

__device__ __forceinline__ ull pk2(float lo, float hi) {
    ull r; asm("mov.b64 %0, {%1, %2};" : "=l"(r) : "f"(lo), "f"(hi)); return r;
}
__device__ __forceinline__ void fma2(ull& d, ull a, ull b) {
    asm("fma.rn.f32x2 %0, %1, %2, %3;" : "=l"(d) : "l"(a), "l"(b), "l"(d));
}
__device__ __forceinline__ float2 upk(ull v) {
    float2 f; asm("mov.b64 {%0, %1}, %2;" : "=f"(f.x), "=f"(f.y) : "l"(v)); return f;
}
__device__ __forceinline__ unsigned cvt_tf32(float f) {
    unsigned u; asm("cvt.rna.tf32.f32 %0, %1;" : "=r"(u) : "f"(f)); return u;
}
__device__ __forceinline__ uint4 cvt4(float4 v) {
    return make_uint4(cvt_tf32(v.x), cvt_tf32(v.y), cvt_tf32(v.z), cvt_tf32(v.w));
}
__device__ __forceinline__ void mma_tf32(float* d, uint4 a, uint2 b) {
    asm("mma.sync.aligned.m16n8k8.row.col.f32.tf32.tf32.f32 "
        "{%0,%1,%2,%3}, {%4,%5,%6,%7}, {%8,%9}, {%0,%1,%2,%3};"
        : "+f"(d[0]), "+f"(d[1]), "+f"(d[2]), "+f"(d[3])
        : "r"(a.x), "r"(a.y), "r"(a.z), "r"(a.w), "r"(b.x), "r"(b.y));
}

// ---- tf32-MMA stage GEMM: tasks = (32 x 512 col-tile) x split-K; writes partials ----
// X = concat([Xa|Xb]) rows of 32 (fp32); W row for global col gc:
//   H>0 -> (gc&3)*H + (gc>>2) (gate-interleaved); H==0 -> gc.
// If xaPart: seg0 X[m][c] = tanh(sum_{s<xaNs} xaPart[(s*32+m)*xaStride + c] + xaBias[c]).
__device__ __noinline__ void gstage_mma(
    int tid, int cta, unsigned* sXm, unsigned* sWm,
    int ncolt, int ksplit, int kc,
    const float* Xa, int Ka, const float* Wa, int lda, int cba,
    const float* Xb, int Kb, const float* Wb, int ldb, int cbb,
    int H, float* out, int ostride,
    const float* xaPart, const float* xaBias, int xaNs, int xaStride)
{
    const int lane = tid & 31, wid = tid >> 5;
    const int nb0 = wid * 64;
    const int xm = tid & 31, xq = (tid >> 5) & 3;
    const int ntasks = ncolt * ksplit;

    for (int task = cta; task < ntasks; task += G) {
        const int ct = task % ncolt, ks = task / ncolt;
        const int kbeg = ks * kc, kend = kbeg + kc;
        float acc[2][8][4];
#pragma unroll
        for (int mt = 0; mt < 2; mt++)
#pragma unroll
            for (int j = 0; j < 8; j++)
#pragma unroll
                for (int r = 0; r < 4; r++) acc[mt][j][r] = 0.f;
        int base = 0;
#pragma unroll 1
        for (int seg = 0; seg < 2; seg++) {
            const float* Xp = seg ? Xb : Xa;
            const float* Wp = seg ? Wb : Wa;
            const int K = seg ? Kb : Ka, ld = seg ? ldb : lda, cb = seg ? cbb : cba;
            if (K > 0) {
                int lo = kbeg > base ? kbeg : base;
                int hi = kend < base + K ? kend : base + K;
                if (lo < hi) {
                    const bool fuse = (seg == 0) && (xaPart != nullptr);
                    const float* xrow = fuse ? nullptr : (Xp + (size_t)xm * K);
                    const float* wp[8];
#pragma unroll
                    for (int j = 0; j < 8; j++) {
                        int i = tid + j * 256;
                        int c = i & 511, kq = i >> 9;
                        int gc = ct * 512 + c;
                        int wr = (H > 0) ? ((gc & 3) * H + (gc >> 2)) : gc;
                        wp[j] = Wp + (size_t)wr * ld + cb + kq * 4;
                    }
                    float4 rx = make_float4(0.f, 0.f, 0.f, 0.f);
                    float4 rw[8];

#define LOADX(xo)                                                                 \
    if (tid < 128) {                                                              \
        if (fuse) {                                                               \
            int col0 = (xo) + xq * 4;                                             \
            float4 s = *(const float4*)&xaBias[col0];                             \
            for (int sp = 0; sp < xaNs; sp++) {                                   \
                float4 p = __ldcg((const float4*)&xaPart[(size_t)(sp * 32 + xm) * xaStride + col0]); \
                s.x += p.x; s.y += p.y; s.z += p.z; s.w += p.w;                    \
            }                                                                     \
            rx = make_float4(tanhf(s.x), tanhf(s.y), tanhf(s.z), tanhf(s.w));     \
        } else {                                                                  \
            rx = __ldcg((const float4*)(xrow + (xo) + xq * 4));                   \
        }                                                                         \
    }
#define LOADW(xo)                                                                 \
    _Pragma("unroll")                                                             \
    for (int j = 0; j < 8; j++) rw[j] = __ldg((const float4*)(wp[j] + (xo)));

                    LOADX(lo - base);
                    LOADW(lo - base);
#pragma unroll 1
                    for (int k0 = lo; k0 < hi; k0 += 16) {
                        if (tid < 128)
                            *(uint4*)&sXm[xm * 20 + xq * 4] = cvt4(rx);
#pragma unroll
                        for (int j = 0; j < 8; j++) {
                            int i = tid + j * 256;
                            int c = i & 511, kq = i >> 9;
                            *(uint4*)&sWm[c * 20 + kq * 4] = cvt4(rw[j]);
                        }
                        __syncthreads();
                        if (k0 + 16 < hi) { LOADX(k0 + 16 - base); LOADW(k0 + 16 - base); }
#pragma unroll
                        for (int kk = 0; kk < 2; kk++) {
                            int kb = kk * 8 + (lane & 3);
                            uint4 af[2];
#pragma unroll
                            for (int mt = 0; mt < 2; mt++) {
                                int r0 = mt * 16 + (lane >> 2);
                                af[mt].x = sXm[r0 * 20 + kb];
                                af[mt].y = sXm[(r0 + 8) * 20 + kb];
                                af[mt].z = sXm[r0 * 20 + kb + 4];
                                af[mt].w = sXm[(r0 + 8) * 20 + kb + 4];
                            }
#pragma unroll
                            for (int j = 0; j < 8; j++) {
                                int n = nb0 + j * 8 + (lane >> 2);
                                uint2 bf = make_uint2(sWm[n * 20 + kb], sWm[n * 20 + kb + 4]);
                                mma_tf32(acc[0][j], af[0], bf);
                                mma_tf32(acc[1][j], af[1], bf);
                            }
                        }
                        __syncthreads();
                    }
#undef LOADX
#undef LOADW
                }
            }
            base += K;
        }
#pragma unroll
        for (int mt = 0; mt < 2; mt++) {
            int row = mt * 16 + (lane >> 2);
#pragma unroll
            for (int j = 0; j < 8; j++) {
                int col = ct * 512 + nb0 + j * 8 + (lane & 3) * 2;
                *(float2*)&out[(size_t)(ks * 32 + row) * ostride + col] =
                    make_float2(acc[mt][j][0], acc[mt][j][1]);
                *(float2*)&out[(size_t)(ks * 32 + row + 8) * ostride + col] =
                    make_float2(acc[mt][j][2], acc[mt][j][3]);
            }
        }
    }
}

// ---- small fp32 f32x2 stage (stage E only: lastp partials, K=256) ----
__device__ __noinline__ void gstage_e(
    int tid, int cta, float* sX, float* sW,
    int ksplit, int kc, const float* Xa, int Ka, const float* Wa, int lda,
    float* out, int ostride)
{
    constexpr int WSTR = 264;
    const int rg = tid / 32, cg = tid % 32;
    const int xm = tid & 31, xq = (tid >> 5) & 3;
    for (int task = cta; task < ksplit; task += G) {
        const int lo = task * kc, hi = lo + kc;
        ull acc[4][4];
#pragma unroll
        for (int r = 0; r < 4; r++)
#pragma unroll
            for (int c = 0; c < 4; c++) acc[r][c] = 0ull;
        const float* xrow = Xa + (size_t)xm * Ka;
        const float* wp[4];
#pragma unroll
        for (int j = 0; j < 4; j++) {
            int i = tid + j * 256;
            int c = i & 255, kq = i >> 8;
            wp[j] = Wa + (size_t)c * lda + kq * 4;
        }
#pragma unroll 1
        for (int k0 = lo; k0 < hi; k0 += 16) {
            if (tid < 128) {
                float4 v = __ldcg((const float4*)(xrow + k0 + xq * 4));
                sX[(xq * 4 + 0) * 36 + xm] = v.x; sX[(xq * 4 + 1) * 36 + xm] = v.y;
                sX[(xq * 4 + 2) * 36 + xm] = v.z; sX[(xq * 4 + 3) * 36 + xm] = v.w;
            }
#pragma unroll
            for (int j = 0; j < 4; j++) {
                int i = tid + j * 256;
                int c = i & 255, kq4 = (i >> 8) * 4;
                float4 v = __ldg((const float4*)(wp[j] + k0));
                sW[(kq4 + 0) * WSTR + c] = v.x; sW[(kq4 + 1) * WSTR + c] = v.y;
                sW[(kq4 + 2) * WSTR + c] = v.z; sW[(kq4 + 3) * WSTR + c] = v.w;
            }
            __syncthreads();
#pragma unroll
            for (int k = 0; k < 16; k++) {
                float4 a = *(const float4*)&sX[k * 36 + rg * 4];
                const float* br = &sW[k * WSTR + cg * 8];
                float4 b0 = *(const float4*)br, b1 = *(const float4*)(br + 4);
                ull bp0 = pk2(b0.x, b0.y), bp1 = pk2(b0.z, b0.w);
                ull bp2 = pk2(b1.x, b1.y), bp3 = pk2(b1.z, b1.w);
                float av[4] = {a.x, a.y, a.z, a.w};
#pragma unroll
                for (int r = 0; r < 4; r++) {
                    ull ad = pk2(av[r], av[r]);
                    fma2(acc[r][0], ad, bp0);
                    fma2(acc[r][1], ad, bp1);
                    fma2(acc[r][2], ad, bp2);
                    fma2(acc[r][3], ad, bp3);
                }
            }
            __syncthreads();
        }
#pragma unroll
        for (int r = 0; r < 4; r++) {
            float2 p0 = upk(acc[r][0]), p1 = upk(acc[r][1]);
            float2 p2 = upk(acc[r][2]), p3 = upk(acc[r][3]);
            float* op = &out[(size_t)(task * 32 + rg * 4 + r) * ostride + cg * 8];
            *(float4*)op = make_float4(p0.x, p0.y, p1.x, p1.y);
            *(float4*)(op + 4) = make_float4(p2.x, p2.y, p3.x, p3.y);
        }
    }
}

__global__ void __launch_bounds__(256, 1) k_loop(
    const float* __restrict__ w2p_W, const float* __restrict__ w2p_b,
    const float* __restrict__ p2w_W, const float* __restrict__ p2w_b,
    const float* __restrict__ p_Wih0, const float* __restrict__ p_Whh0,
    const float* __restrict__ p_bih0, const float* __restrict__ p_bhh0,
    const float* __restrict__ w_Wih0, const float* __restrict__ w_Whh0,
    const float* __restrict__ w_bih0, const float* __restrict__ w_bhh0,
    const float* __restrict__ w_Wih1, const float* __restrict__ w_Whh1,
    const float* __restrict__ w_bih1, const float* __restrict__ w_bhh1,
    const float* __restrict__ pos_proj_W, const float* __restrict__ pos_proj_b,
    float* __restrict__ pout)
{
    __shared__ unsigned shm[10880];          // sWm[512*20] + sXm[32*20]
    unsigned* sWm = shm;
    unsigned* sXm = shm + 10240;
    float* sXf = (float*)shm;                // stage E aliases
    float* sWf = (float*)(shm + 16 * 36);
    const int tid = threadIdx.x, cta = blockIdx.x;
    const int gt = cta * 256 + tid;

    {
        float4 z = make_float4(0.f, 0.f, 0.f, 0.f);
        if (gt < 2048) { ((float4*)g_ph)[gt] = z; ((float4*)g_pc)[gt] = z; }
        if (gt < 8192) { ((float4*)g_wh0)[gt] = z; ((float4*)g_wc0)[gt] = z;
                         ((float4*)g_wh1)[gt] = z; ((float4*)g_wc1)[gt] = z; }
    }
    gridbar();

    for (int t = 0; t < TT; t++) {
        // A: pbuf[0..] = wh1 @ w2p_W^T  (1024 cols, K=1024, 2x32 tasks, kc 32)
        gstage_mma(tid, cta, sXm, sWm, 2, 32, 32,
                   g_wh1, 1024, w2p_W, 1024, 0,
                   nullptr, 0, nullptr, 0, 0,
                   0, g_pbuf, 1024, nullptr, nullptr, 0, 0);
        gridbar();
        // C: pos gates (K = lastw 1024 fused-from-A-partials + ph 256), 2x40, kc 32
        gstage_mma(tid, cta, sXm, sWm, 2, 40, 32,
                   nullptr, 1024, p_Wih0, 1152, 128,
                   g_ph, 256, p_Whh0, 256, 0,
                   256, g_pbuf + PBUF_C, 1024, g_pbuf, w2p_b, 32, 1024);
        gridbar();
        // D: pos cell update (40 partials)
        for (int gid = gt; gid < 8192; gid += G * 256) {
            int m = gid >> 8, u = gid & 255;
            float4 s = __ldg((const float4*)&g_PIH[(size_t)(t * 32 + m) * 1024 + u * 4]);
#pragma unroll
            for (int ks = 0; ks < 40; ks++) {
                float4 p = __ldcg((const float4*)&g_pbuf[PBUF_C + (size_t)(ks * 32 + m) * 1024 + u * 4]);
                s.x += p.x; s.y += p.y; s.z += p.z; s.w += p.w;
            }
            float iv = sigf(s.x + __ldg(&p_bih0[u]) + __ldg(&p_bhh0[u]));
            float fv = sigf(s.y + __ldg(&p_bih0[256 + u]) + __ldg(&p_bhh0[256 + u]));
            float gv = tanhf(s.z + __ldg(&p_bih0[512 + u]) + __ldg(&p_bhh0[512 + u]));
            float ov = sigf(s.w + __ldg(&p_bih0[768 + u]) + __ldg(&p_bhh0[768 + u]));
            float c = fv * __ldcg(&g_pc[gid]) + iv * gv;
            g_pc[gid] = c; g_ph[gid] = ov * tanhf(c);
        }
        gridbar();
        // E: lastp partials (CTAs 0-7) + pos logits (CTAs 8-39)
        gstage_e(tid, cta, sXf, sWf, 8, 32, g_ph, 256, p2w_W, 256, g_pbufE, 256);
        if (cta >= 8 && cta < 40) {
            int r = cta - 8;
            float v = 0.f;
            float* sred = (float*)shm + 9000;
            if (tid < 48) {
                v = __ldg(&pos_proj_b[tid]);
                const float4* xp = (const float4*)(g_ph + r * 256);
                const float4* wp = (const float4*)(pos_proj_W + tid * 256);
#pragma unroll 8
                for (int k = 0; k < 64; k++) {
                    float4 x = __ldcg(xp + k), w = __ldg(wp + k);
                    v = fmaf(x.x, w.x, v); v = fmaf(x.y, w.y, v);
                    v = fmaf(x.z, w.z, v); v = fmaf(x.w, w.w, v);
                }
                sred[tid] = v;
            }
            __syncthreads();
            if (tid == 0) {
                float mx = -1e30f;
                for (int k = 0; k < 48; k++) mx = fmaxf(mx, sred[k]);
                float sm = 0.f;
                for (int k = 0; k < 48; k++) sm += expf(sred[k] - mx);
                sred[48] = mx + logf(sm);
            }
            __syncthreads();
            if (tid < 48) pout[((size_t)t * 32 + r) * 48 + tid] = v - sred[48];
        }
        gridbar();
        // F: word LSTM0 gates (K = lastp 256 fused + wh0 1024), 8x16, kc 80
        gstage_mma(tid, cta, sXm, sWm, 8, 16, 80,
                   nullptr, 256, w_Wih0, 768, 512,
                   g_wh0, 1024, w_Whh0, 1024, 0,
                   1024, g_pbuf, 4096, g_pbufE, p2w_b, 8, 256);
        gridbar();
        // G: word LSTM0 cell
        for (int gid = gt; gid < 32768; gid += G * 256) {
            int m = gid >> 10, u = gid & 1023;
            float4 s = __ldg((const float4*)&g_WIH0[(size_t)(t * 32 + m) * 4096 + u * 4]);
#pragma unroll
            for (int ks = 0; ks < 16; ks++) {
                float4 p = __ldcg((const float4*)&g_pbuf[(size_t)(ks * 32 + m) * 4096 + u * 4]);
                s.x += p.x; s.y += p.y; s.z += p.z; s.w += p.w;
            }
            float iv = sigf(s.x + __ldg(&w_bih0[u]) + __ldg(&w_bhh0[u]));
            float fv = sigf(s.y + __ldg(&w_bih0[1024 + u]) + __ldg(&w_bhh0[1024 + u]));
            float gv = tanhf(s.z + __ldg(&w_bih0[2048 + u]) + __ldg(&w_bhh0[2048 + u]));
            float ov = sigf(s.w + __ldg(&w_bih0[3072 + u]) + __ldg(&w_bhh0[3072 + u]));
            float c = fv * __ldcg(&g_wc0[gid]) + iv * gv;
            g_wc0[gid] = c; g_wh0[gid] = ov * tanhf(c);
        }
        gridbar();
        // H: word LSTM1 gates (K = wh0 1024 + wh1 1024), 8x16, kc 128
        gstage_mma(tid, cta, sXm, sWm, 8, 16, 128,
                   g_wh0, 1024, w_Wih1, 1024, 0,
                   g_wh1, 1024, w_Whh1, 1024, 0,
                   1024, g_pbuf, 4096, nullptr, nullptr, 0, 0);
        gridbar();
        // I: word LSTM1 cell (+ history store for hoisted e GEMM)
        for (int gid = gt; gid < 32768; gid += G * 256) {
            int m = gid >> 10, u = gid & 1023;
            float4 s = make_float4(0.f, 0.f, 0.f, 0.f);
#pragma unroll
            for (int ks = 0; ks < 16; ks++) {
                float4 p = __ldcg((const float4*)&g_pbuf[(size_t)(ks * 32 + m) * 4096 + u * 4]);
                s.x += p.x; s.y += p.y; s.z += p.z; s.w += p.w;
            }
            float iv = sigf(s.x + __ldg(&w_bih1[u]) + __ldg(&w_bhh1[u]));
            float fv = sigf(s.y + __ldg(&w_bih1[1024 + u]) + __ldg(&w_bhh1[1024 + u]));
            float gv = tanhf(s.z + __ldg(&w_bih1[2048 + u]) + __ldg(&w_bhh1[2048 + u]));
            float ov = sigf(s.w + __ldg(&w_bih1[3072 + u]) + __ldg(&w_bhh1[3072 + u]));
            float c = fv * __ldcg(&g_wc1[gid]) + iv * gv;
            g_wc1[gid] = c;
            float h = ov * tanhf(c);
            g_wh1[gid] = h;
            g_whist[(size_t)t * 32768 + gid] = h;
        }
        gridbar();
    }
}

// ---- generic tf32 mma GEMM: out[2048][N] = A(gather?) @ Wrow(map)^T (+bias) ----
// tile 64m x 128n, 256 thr = 8 warps (2m x 4n), K-chunk 32, natural [row][k] smem.
__global__ void __launch_bounds__(256, 2) k_mmagen(
    const int* __restrict__ idx, const float* __restrict__ A, int K,
    const float* __restrict__ W, int ldW, int H,
    const float* __restrict__ bias, float* __restrict__ out, int N)
{
    __shared__ unsigned sA[64 * 36];
    __shared__ unsigned sB[128 * 36];
    const int tid = threadIdx.x, lane = tid & 31, wid = tid >> 5;
    const int wm = wid & 1, wn = wid >> 1;
    const int mb = blockIdx.y * 64, nb = blockIdx.x * 128;

    float acc[2][4][4];
#pragma unroll
    for (int mt = 0; mt < 2; mt++)
#pragma unroll
        for (int j = 0; j < 4; j++)
#pragma unroll
            for (int r = 0; r < 4; r++) acc[mt][j][r] = 0.f;

    const float* aptr[2]; unsigned* sa[2];
    const float* wptr[4]; unsigned* sb[4];
#pragma unroll
    for (int j = 0; j < 2; j++) {
        int i = tid * 2 + j, m = i >> 3, kq = i & 7;
        const float* rowp = idx ? (A + (size_t)__ldg(&idx[mb + m]) * K)
                                : (A + (size_t)(mb + m) * K);
        aptr[j] = rowp + kq * 4;
        sa[j] = &sA[m * 36 + kq * 4];
    }
#pragma unroll
    for (int j = 0; j < 4; j++) {
        int i = tid * 4 + j, n = i >> 3, kq = i & 7;
        int gc = nb + n;
        int wr = (H > 0) ? ((gc & 3) * H + (gc >> 2)) : gc;
        wptr[j] = W + (size_t)wr * ldW + kq * 4;
        sb[j] = &sB[n * 36 + kq * 4];
    }
    const int arow = wm * 32 + (lane >> 2);
    const int kcol0 = lane & 3;
    const int nrow0 = wn * 32 + (lane >> 2);

    const int nch = K / 32;
    float4 av[2], wv[4];
#define LDE(c)                                                        \
    { _Pragma("unroll") for (int j = 0; j < 2; j++) av[j] = __ldcg((const float4*)(aptr[j] + (c) * 32)); \
      _Pragma("unroll") for (int j = 0; j < 4; j++) wv[j] = __ldg((const float4*)(wptr[j] + (c) * 32)); }

    LDE(0);
#pragma unroll 1
    for (int c = 0; c < nch; c++) {
#pragma unroll
        for (int j = 0; j < 2; j++) *(uint4*)sa[j] = cvt4(av[j]);
#pragma unroll
        for (int j = 0; j < 4; j++) *(uint4*)sb[j] = cvt4(wv[j]);
        __syncthreads();
        if (c + 1 < nch) LDE(c + 1);
#pragma unroll
        for (int kk = 0; kk < 4; kk++) {
            int kc0 = kk * 8 + kcol0;
            uint4 af[2];
#pragma unroll
            for (int mt = 0; mt < 2; mt++) {
                int r0 = arow + mt * 16;
                af[mt].x = sA[r0 * 36 + kc0];
                af[mt].y = sA[(r0 + 8) * 36 + kc0];
                af[mt].z = sA[r0 * 36 + kc0 + 4];
                af[mt].w = sA[(r0 + 8) * 36 + kc0 + 4];
            }
#pragma unroll
            for (int j = 0; j < 4; j++) {
                int nr = nrow0 + j * 8;
                uint2 bf = make_uint2(sB[nr * 36 + kc0], sB[nr * 36 + kc0 + 4]);
                mma_tf32(acc[0][j], af[0], bf);
                mma_tf32(acc[1][j], af[1], bf);
            }
        }
        __syncthreads();
    }
#undef LDE

#pragma unroll
    for (int mt = 0; mt < 2; mt++) {
        int row0 = mb + wm * 32 + mt * 16 + (lane >> 2);
#pragma unroll
        for (int j = 0; j < 4; j++) {
            int col0 = nb + wn * 32 + j * 8 + (lane & 3) * 2;
            float2 bv = bias ? *(const float2*)&bias[col0] : make_float2(0.f, 0.f);
            *(float2*)&out[(size_t)row0 * N + col0] =
                make_float2(acc[mt][j][0] + bv.x, acc[mt][j][1] + bv.y);
            *(float2*)&out[(size_t)(row0 + 8) * N + col0] =
                make_float2(acc[mt][j][2] + bv.x, acc[mt][j][3] + bv.y);
        }
    }
}

__global__ void k_wnorm(float* __restrict__ wout)
{
    float* p = wout + (size_t)blockIdx.x * WORD_V;
    __shared__ float red[256];
    int tid = threadIdx.x;
    float m = -1e30f;
    for (int k = tid; k < WORD_V; k += 256) m = fmaxf(m, p[k]);
    red[tid] = m; __syncthreads();
    for (int s = 128; s > 0; s >>= 1) { if (tid < s) red[tid] = fmaxf(red[tid], red[tid + s]); __syncthreads(); }
    m = red[0]; __syncthreads();
    float s = 0.f;
    for (int k = tid; k < WORD_V; k += 256) s += expf(p[k] - m);
    red[tid] = s; __syncthreads();
    for (int st = 128; st > 0; st >>= 1) { if (tid < st) red[tid] += red[tid + st]; __syncthreads(); }
    float lse = m + logf(red[0]);
    for (int k = tid; k < WORD_V; k += 256) p[k] -= lse;
}

extern "C" void kernel_launch(void* const* d_in, const int* in_sizes, int n_in,
                              void* d_out, int out_size)
{
    const int*   pos          = (const int*)  d_in[0];
    const int*   word         = (const int*)  d_in[1];
    const float* pos_emb_W    = (const float*)d_in[2];
    const float* word_emb_W   = (const float*)d_in[3];
    const float* w2p_W        = (const float*)d_in[4];
    const float* w2p_b        = (const float*)d_in[5];
    const float* p2w_W        = (const float*)d_in[6];
    const float* p2w_b        = (const float*)d_in[7];
    const float* p_Wih0       = (const float*)d_in[8];
    const float* p_Whh0       = (const float*)d_in[9];
    const float* p_bih0       = (const float*)d_in[10];
    const float* p_bhh0       = (const float*)d_in[11];
    const float* w_Wih0       = (const float*)d_in[12];
    const float* w_Whh0       = (const float*)d_in[13];
    const float* w_bih0       = (const float*)d_in[14];
    const float* w_bhh0       = (const float*)d_in[15];
    const float* w_Wih1       = (const float*)d_in[16];
    const float* w_Whh1       = (const float*)d_in[17];
    const float* w_bih1       = (const float*)d_in[18];
    const float* w_bhh1       = (const float*)d_in[19];
    const float* pos_proj_W   = (const float*)d_in[20];
    const float* pos_proj_b   = (const float*)d_in[21];
    const float* word_proj1_W = (const float*)d_in[22];
    const float* word_proj1_b = (const float*)d_in[23];
    const float* word_proj2_b = (const float*)d_in[24];

    float* pih = nullptr;   cudaGetSymbolAddress((void**)&pih,   g_PIH);
    float* wih = nullptr;   cudaGetSymbolAddress((void**)&wih,   g_WIH0);
    float* whist = nullptr; cudaGetSymbolAddress((void**)&whist, g_whist);
    float* ebuf = nullptr;  cudaGetSymbolAddress((void**)&ebuf,  g_ebuf);

    float* pout = (float*)d_out;
    float* wout = pout + (size_t)TT * 32 * 48;

    // hoisted input projections (token-indexed, independent of recurrence)
    k_mmagen<<<dim3(8, 32), 256>>>(pos, pos_emb_W, 128, p_Wih0, 1152, 256,
                                   nullptr, pih, 1024);
    k_mmagen<<<dim3(32, 32), 256>>>(word, word_emb_W, 512, w_Wih0, 768, 1024,
                                    nullptr, wih, 4096);

    // the whole 64-step recurrence in ONE persistent kernel
    k_loop<<<G, 256>>>(w2p_W, w2p_b, p2w_W, p2w_b,
                       p_Wih0, p_Whh0, p_bih0, p_bhh0,
                       w_Wih0, w_Whh0, w_bih0, w_bhh0,
                       w_Wih1, w_Whh1, w_bih1, w_bhh1,
                       pos_proj_W, pos_proj_b, pout);

    // hoisted e = WH1hist @ proj1^T + b, then logits GEMM, then log-softmax
    k_mmagen<<<dim3(4, 32), 256>>>(nullptr, whist, 1024, word_proj1_W, 1024, 0,
                                   word_proj1_b, ebuf, 512);
    k_mmagen<<<dim3(WORD_V / 128, 32), 256>>>(nullptr, ebuf, 512, word_emb_W, 512, 0,
                                              word_proj2_b, wout, WORD_V);
    k_wnorm<<<TT * 32, 256>>>(wout);
}